// round 3
// baseline (speedup 1.0000x reference)
#include <cuda_runtime.h>
#include <cuda_bf16.h>
#include <math.h>

#define BATCH   2
#define SEQ     2048
#define DMODEL  2048
#define NHEADS  32
#define HDIM    64
#define KVHEADS 8
#define MROWS   (BATCH*SEQ)          // 4096

// ---------------- scratch (device globals; no allocation allowed) ----------
__device__ float g_Q[MROWS * NHEADS * HDIM];    // 4096 x 2048
__device__ float g_K[MROWS * KVHEADS * HDIM];   // 4096 x 512
__device__ float g_V[MROWS * KVHEADS * HDIM];   // 4096 x 512
__device__ float g_O[MROWS * NHEADS * HDIM];    // 4096 x 2048
__device__ float g_freqs[32];

// ---------------- RoPE frequency table (double-accurate, mimics jnp fp32) --
__global__ void init_freqs_kernel() {
    int i = threadIdx.x;  // 32 threads
    // freqs[i] = 10000^(-i/32) = exp2(-i * log2(10000)/32)
    g_freqs[i] = (float)exp2(-(double)i * (13.287712379549449 / 32.0));
}

// ---------------- SGEMM: C(MxN) = A(MxK) @ B(KxN), all row-major ----------
// 128x128 block tile, BK=8, 256 threads, 8x8 per-thread micro-tile.
__global__ void __launch_bounds__(256) sgemm_kernel(
    const float* __restrict__ A, const float* __restrict__ B,
    float* __restrict__ C, int M, int N, int K)
{
    __shared__ float As[8][128];
    __shared__ float Bs[8][128];

    const int tid = threadIdx.x;
    const int bx = blockIdx.x, by = blockIdx.y;
    const int tx = tid & 15, ty = tid >> 4;

    // loaders: A tile 128x8 (one float4/thread), B tile 8x128 (one float4/thread)
    const int arow  = tid >> 1;
    const int acol4 = (tid & 1) * 4;
    const int brow  = tid >> 5;
    const int bcol4 = (tid & 31) * 4;

    const float* Ab = A + (size_t)(by * 128 + arow) * K + acol4;
    const float* Bb = B + (size_t)brow * N + bx * 128 + bcol4;

    float acc[8][8];
#pragma unroll
    for (int i = 0; i < 8; i++)
#pragma unroll
        for (int j = 0; j < 8; j++) acc[i][j] = 0.0f;

    for (int kb = 0; kb < K; kb += 8) {
        const float4 a  = *(const float4*)(Ab + kb);
        const float4 bv = *(const float4*)(Bb + (size_t)kb * N);
        __syncthreads();
        As[acol4 + 0][arow] = a.x;
        As[acol4 + 1][arow] = a.y;
        As[acol4 + 2][arow] = a.z;
        As[acol4 + 3][arow] = a.w;
        *(float4*)&Bs[brow][bcol4] = bv;
        __syncthreads();
#pragma unroll
        for (int k = 0; k < 8; k++) {
            float ar[8], br[8];
            *(float4*)(ar)     = *(const float4*)&As[k][ty * 8];
            *(float4*)(ar + 4) = *(const float4*)&As[k][ty * 8 + 4];
            *(float4*)(br)     = *(const float4*)&Bs[k][tx * 8];
            *(float4*)(br + 4) = *(const float4*)&Bs[k][tx * 8 + 4];
#pragma unroll
            for (int i = 0; i < 8; i++)
#pragma unroll
                for (int j = 0; j < 8; j++)
                    acc[i][j] += ar[i] * br[j];
        }
    }

#pragma unroll
    for (int i = 0; i < 8; i++) {
        const size_t off = (size_t)(by * 128 + ty * 8 + i) * N + bx * 128 + tx * 8;
        float4 c0 = make_float4(acc[i][0], acc[i][1], acc[i][2], acc[i][3]);
        float4 c1 = make_float4(acc[i][4], acc[i][5], acc[i][6], acc[i][7]);
        *(float4*)(C + off)     = c0;
        *(float4*)(C + off + 4) = c1;
    }
}

// ---------------- RoPE (in place), matches reference's repeated-freq form --
// out[j]    = x[j]*cos(t*f[j/2])      - x[j+32]*sin(t*f[j/2])       (j<32)
// out[32+j] = x[j]*sin(t*f[16+j/2])   + x[j+32]*cos(t*f[16+j/2])
__global__ void rope_kernel(float* __restrict__ buf, int rowlen, int heads)
{
    const int idx = blockIdx.x * blockDim.x + threadIdx.x;
    const int total = MROWS * heads * 32;
    if (idx >= total) return;
    const int j  = idx & 31;
    const int t1 = idx >> 5;
    const int h  = t1 % heads;
    const int r  = t1 / heads;           // global row = b*SEQ + n
    const float tn = (float)(r & (SEQ - 1));

    float* p = buf + (size_t)r * rowlen + h * HDIM;
    const float x1 = p[j];
    const float x2 = p[j + 32];

    const float a1 = tn * g_freqs[j >> 1];
    const float a2 = tn * g_freqs[16 + (j >> 1)];
    float s1, c1, s2, c2;
    sincosf(a1, &s1, &c1);
    sincosf(a2, &s2, &c2);
    p[j]      = x1 * c1 - x2 * s1;
    p[j + 32] = x1 * s2 + x2 * c2;
}

// ---------------- Flash attention (fp32), causal + ALiBi + pad mask -------
// One block per (q-tile of 64, head, batch). 256 threads as 16x16,
// 4x4 micro-tiles. Smem tiles 64x64 fp32 with XOR-line swizzle
// (phys_line = line ^ (row>>2)) -> all LDS.128 conflict-free.
#define SWOFF(row, line) (((row) << 6) + ((((line) ^ ((row) >> 2)) & 15) << 2))

__global__ void __launch_bounds__(256, 2) flash_kernel(
    const float* __restrict__ Q, const float* __restrict__ K,
    const float* __restrict__ V, const int* __restrict__ mask,
    float* __restrict__ O)
{
    extern __shared__ float smem[];
    float* Qs = smem;            // 64x64
    float* Ks = smem + 4096;
    float* Vs = smem + 8192;
    float* Ps = smem + 12288;

    const int qt = blockIdx.x, h = blockIdx.y, b = blockIdx.z;
    const int kvh = h >> 2;
    const int tid = threadIdx.x;
    const int tx = tid & 15, ty = tid >> 4;
    const int r0 = ty * 4, c0 = tx * 4;
    const float scale = 0.125f;                       // 64^-0.5
    const float slope = exp2f(-0.25f * (float)(h + 1));

    // load Q tile (rows qt*64.., head cols)
#pragma unroll
    for (int i = tid; i < 1024; i += 256) {
        const int row = i >> 4, l = i & 15;
        const float4 v = *(const float4*)(
            Q + (size_t)(b * SEQ + qt * 64 + row) * (NHEADS * HDIM) + h * HDIM + l * 4);
        *(float4*)(Qs + SWOFF(row, l)) = v;
    }

    float m_i[4], l_i[4], acc[4][4];
#pragma unroll
    for (int i = 0; i < 4; i++) {
        m_i[i] = -1e30f; l_i[i] = 0.0f;
#pragma unroll
        for (int j = 0; j < 4; j++) acc[i][j] = 0.0f;
    }

    for (int kt = 0; kt <= qt; kt++) {
        __syncthreads();
#pragma unroll
        for (int i = tid; i < 1024; i += 256) {
            const int row = i >> 4, l = i & 15;
            const size_t g = (size_t)(b * SEQ + kt * 64 + row) * (KVHEADS * HDIM) + kvh * HDIM + l * 4;
            const int off = SWOFF(row, l);
            *(float4*)(Ks + off) = *(const float4*)(K + g);
            *(float4*)(Vs + off) = *(const float4*)(V + g);
        }
        __syncthreads();

        // S = Q K^T (4x4 micro)
        float s[4][4];
#pragma unroll
        for (int i = 0; i < 4; i++)
#pragma unroll
            for (int j = 0; j < 4; j++) s[i][j] = 0.0f;

#pragma unroll
        for (int dl = 0; dl < 16; dl++) {
            float4 qv[4], kv[4];
#pragma unroll
            for (int i = 0; i < 4; i++) qv[i] = *(const float4*)(Qs + ((r0 + i) << 6) + (((dl ^ ty) & 15) << 2));
#pragma unroll
            for (int j = 0; j < 4; j++) kv[j] = *(const float4*)(Ks + ((c0 + j) << 6) + (((dl ^ tx) & 15) << 2));
#pragma unroll
            for (int i = 0; i < 4; i++) {
                const float* qa = (const float*)&qv[i];
#pragma unroll
                for (int j = 0; j < 4; j++) {
                    const float* ka = (const float*)&kv[j];
                    s[i][j] += qa[0] * ka[0] + qa[1] * ka[1] + qa[2] * ka[2] + qa[3] * ka[3];
                }
            }
        }

        // scale + ALiBi(key-absolute) + causal + pad mask
        const int qg0 = qt * 64 + r0;
        const int kg0 = kt * 64 + c0;
        int pm[4];
#pragma unroll
        for (int j = 0; j < 4; j++) pm[j] = __ldg(mask + b * SEQ + kg0 + j);
#pragma unroll
        for (int i = 0; i < 4; i++)
#pragma unroll
            for (int j = 0; j < 4; j++) {
                const int kg = kg0 + j;
                float v = s[i][j] * scale + slope * (float)kg;
                if (kg > qg0 + i || pm[j] == 0) v = -1e30f;
                s[i][j] = v;
            }

        // online softmax update (row stats shared across 16 lanes)
#pragma unroll
        for (int i = 0; i < 4; i++) {
            float mx = fmaxf(fmaxf(s[i][0], s[i][1]), fmaxf(s[i][2], s[i][3]));
            mx = fmaxf(mx, __shfl_xor_sync(0xffffffffu, mx, 1));
            mx = fmaxf(mx, __shfl_xor_sync(0xffffffffu, mx, 2));
            mx = fmaxf(mx, __shfl_xor_sync(0xffffffffu, mx, 4));
            mx = fmaxf(mx, __shfl_xor_sync(0xffffffffu, mx, 8));
            const float mnew = fmaxf(m_i[i], mx);
            const float corr = __expf(m_i[i] - mnew);
            float ps = 0.0f;
#pragma unroll
            for (int j = 0; j < 4; j++) { const float p = __expf(s[i][j] - mnew); s[i][j] = p; ps += p; }
            ps += __shfl_xor_sync(0xffffffffu, ps, 1);
            ps += __shfl_xor_sync(0xffffffffu, ps, 2);
            ps += __shfl_xor_sync(0xffffffffu, ps, 4);
            ps += __shfl_xor_sync(0xffffffffu, ps, 8);
            l_i[i] = l_i[i] * corr + ps;
            m_i[i] = mnew;
#pragma unroll
            for (int j = 0; j < 4; j++) acc[i][j] *= corr;
            // write P row (line = tx, row-swizzle = ty)
            *(float4*)(Ps + ((r0 + i) << 6) + (((tx ^ ty) & 15) << 2)) =
                make_float4(s[i][0], s[i][1], s[i][2], s[i][3]);
        }
        __syncthreads();

        // O += P V
#pragma unroll
        for (int cl = 0; cl < 16; cl++) {
            float4 pvv[4], vvv[4];
#pragma unroll
            for (int i = 0; i < 4; i++) pvv[i] = *(const float4*)(Ps + ((r0 + i) << 6) + (((cl ^ ty) & 15) << 2));
#pragma unroll
            for (int k = 0; k < 4; k++) vvv[k] = *(const float4*)(Vs + ((cl * 4 + k) << 6) + (((tx ^ cl) & 15) << 2));
#pragma unroll
            for (int i = 0; i < 4; i++) {
                const float* pp = (const float*)&pvv[i];
#pragma unroll
                for (int k = 0; k < 4; k++) {
                    const float  pk = pp[k];
                    const float* vk = (const float*)&vvv[k];
                    acc[i][0] += pk * vk[0];
                    acc[i][1] += pk * vk[1];
                    acc[i][2] += pk * vk[2];
                    acc[i][3] += pk * vk[3];
                }
            }
        }
    }

    // epilogue: normalize and store (b, n, h*64+d) layout
#pragma unroll
    for (int i = 0; i < 4; i++) {
        const float inv = 1.0f / l_i[i];
        float4 r = make_float4(acc[i][0] * inv, acc[i][1] * inv, acc[i][2] * inv, acc[i][3] * inv);
        *(float4*)(O + (size_t)(b * SEQ + qt * 64 + r0 + i) * (NHEADS * HDIM) + h * HDIM + c0) = r;
    }
}

// ---------------- host launcher -------------------------------------------
extern "C" void kernel_launch(void* const* d_in, const int* in_sizes, int n_in,
                              void* d_out, int out_size)
{
    const float* x    = (const float*)d_in[0];
    const int*   mask = (const int*)  d_in[1];
    const float* Wq   = (const float*)d_in[2];
    const float* Wk   = (const float*)d_in[3];
    const float* Wv   = (const float*)d_in[4];
    const float* Wo   = (const float*)d_in[5];
    float* out = (float*)d_out;

    void *pQ, *pK, *pV, *pO;
    cudaGetSymbolAddress(&pQ, g_Q);
    cudaGetSymbolAddress(&pK, g_K);
    cudaGetSymbolAddress(&pV, g_V);
    cudaGetSymbolAddress(&pO, g_O);

    init_freqs_kernel<<<1, 32>>>();

    // QKV projections
    sgemm_kernel<<<dim3(2048 / 128, MROWS / 128), 256>>>(x, Wq, (float*)pQ, MROWS, 2048, DMODEL);
    sgemm_kernel<<<dim3(512  / 128, MROWS / 128), 256>>>(x, Wk, (float*)pK, MROWS, 512,  DMODEL);
    sgemm_kernel<<<dim3(512  / 128, MROWS / 128), 256>>>(x, Wv, (float*)pV, MROWS, 512,  DMODEL);

    // RoPE on Q and K
    rope_kernel<<<(MROWS * NHEADS  * 32) / 256, 256>>>((float*)pQ, NHEADS  * HDIM, NHEADS);
    rope_kernel<<<(MROWS * KVHEADS * 32) / 256, 256>>>((float*)pK, KVHEADS * HDIM, KVHEADS);

    // Flash attention
    cudaFuncSetAttribute(flash_kernel, cudaFuncAttributeMaxDynamicSharedMemorySize, 65536);
    flash_kernel<<<dim3(SEQ / 64, NHEADS, BATCH), 256, 65536>>>(
        (const float*)pQ, (const float*)pK, (const float*)pV, mask, (float*)pO);

    // Output projection
    sgemm_kernel<<<dim3(2048 / 128, MROWS / 128), 256>>>((const float*)pO, Wo, out, MROWS, 2048, DMODEL);
}

// round 4
// speedup vs baseline: 1.8327x; 1.8327x over previous
#include <cuda_runtime.h>
#include <cuda_bf16.h>
#include <math.h>

#define BATCH   2
#define SEQ     2048
#define DMODEL  2048
#define NHEADS  32
#define HDIM    64
#define KVHEADS 8
#define MROWS   (BATCH*SEQ)          // 4096

// ---------------- scratch (device globals; no allocation allowed) ----------
__device__ float g_Q[MROWS * NHEADS * HDIM];    // 4096 x 2048
__device__ float g_K[MROWS * KVHEADS * HDIM];   // 4096 x 512
__device__ float g_V[MROWS * KVHEADS * HDIM];   // 4096 x 512
__device__ float g_O[MROWS * NHEADS * HDIM];    // 4096 x 2048
__device__ float g_freqs[32];

// split-bf16 planes
__device__ __nv_bfloat16 g_xh [MROWS * DMODEL];
__device__ __nv_bfloat16 g_xl [MROWS * DMODEL];
__device__ __nv_bfloat16 g_Wqh[DMODEL * 2048];
__device__ __nv_bfloat16 g_Wql[DMODEL * 2048];
__device__ __nv_bfloat16 g_Wkh[DMODEL * 512];
__device__ __nv_bfloat16 g_Wkl[DMODEL * 512];
__device__ __nv_bfloat16 g_Wvh[DMODEL * 512];
__device__ __nv_bfloat16 g_Wvl[DMODEL * 512];
__device__ __nv_bfloat16 g_Woh[2048 * DMODEL];
__device__ __nv_bfloat16 g_Wol[2048 * DMODEL];
__device__ __nv_bfloat16 g_Oh [MROWS * 2048];
__device__ __nv_bfloat16 g_Ol [MROWS * 2048];

// ---------------- RoPE frequency table -------------------------------------
__global__ void init_freqs_kernel() {
    int i = threadIdx.x;  // 32 threads
    g_freqs[i] = (float)exp2(-(double)i * (13.287712379549449 / 32.0));
}

// ---------------- fp32 -> (hi, lo) bf16 split -------------------------------
__global__ void __launch_bounds__(256) split_kernel(
    const float* __restrict__ src, __nv_bfloat16* __restrict__ hi,
    __nv_bfloat16* __restrict__ lo, int n4)
{
    const int i = blockIdx.x * blockDim.x + threadIdx.x;
    if (i >= n4) return;
    const float4 f = ((const float4*)src)[i];
    __nv_bfloat16 h[4], l[4];
    const float fv[4] = {f.x, f.y, f.z, f.w};
#pragma unroll
    for (int k = 0; k < 4; k++) {
        h[k] = __float2bfloat16(fv[k]);
        l[k] = __float2bfloat16(fv[k] - __bfloat162float(h[k]));
    }
    *(uint2*)(hi + 4 * (size_t)i) = *(uint2*)h;
    *(uint2*)(lo + 4 * (size_t)i) = *(uint2*)l;
}

// ---------------- PTX helpers ----------------------------------------------
__device__ __forceinline__ void cpasync16(void* s, const void* g) {
    unsigned sa = (unsigned)__cvta_generic_to_shared(s);
    asm volatile("cp.async.cg.shared.global [%0], [%1], 16;\n" :: "r"(sa), "l"(g));
}
__device__ __forceinline__ void cp_commit() {
    asm volatile("cp.async.commit_group;\n" ::: "memory");
}
__device__ __forceinline__ void cp_wait0() {
    asm volatile("cp.async.wait_group 0;\n" ::: "memory");
}
__device__ __forceinline__ void ldsm4(unsigned* r, const __nv_bfloat16* p) {
    unsigned a = (unsigned)__cvta_generic_to_shared(p);
    asm volatile("ldmatrix.sync.aligned.m8n8.x4.shared.b16 {%0,%1,%2,%3}, [%4];"
                 : "=r"(r[0]), "=r"(r[1]), "=r"(r[2]), "=r"(r[3]) : "r"(a));
}
__device__ __forceinline__ void ldsm4t(unsigned* r, const __nv_bfloat16* p) {
    unsigned a = (unsigned)__cvta_generic_to_shared(p);
    asm volatile("ldmatrix.sync.aligned.m8n8.x4.trans.shared.b16 {%0,%1,%2,%3}, [%4];"
                 : "=r"(r[0]), "=r"(r[1]), "=r"(r[2]), "=r"(r[3]) : "r"(a));
}
__device__ __forceinline__ void mma16816(float* d, const unsigned* a, const unsigned* b) {
    asm volatile("mma.sync.aligned.m16n8k16.row.col.f32.bf16.bf16.f32 "
                 "{%0,%1,%2,%3},{%4,%5,%6,%7},{%8,%9},{%0,%1,%2,%3};"
                 : "+f"(d[0]), "+f"(d[1]), "+f"(d[2]), "+f"(d[3])
                 : "r"(a[0]), "r"(a[1]), "r"(a[2]), "r"(a[3]), "r"(b[0]), "r"(b[1]));
}

// ---------------- split-bf16 3-product tensor-core GEMM ---------------------
// C(MxN) = Ah*Bh + Ah*Bl + Al*Bh, fp32 accum.  A row-major [M,K], B [K,N].
// BM=128 BN=128 BK=32, 256 threads = 8 warps (2 x 4), warp tile 64x32.
#define SA_STRIDE 56   // bf16; 112B row: 16B-aligned, distinct banks for LDSM
#define SB_STRIDE 136  // 272B row
#define SA_PLANE  (128 * SA_STRIDE)   // 7168 elems
#define SB_PLANE  (32 * SB_STRIDE)    // 4352 elems
#define STAGE_ELEMS (2 * SA_PLANE + 2 * SB_PLANE)   // 23040 elems = 46080 B
#define GEMM_SMEM (2 * STAGE_ELEMS * 2)             // 92160 B

__global__ void __launch_bounds__(256, 1) gemm_bf16x3(
    const __nv_bfloat16* __restrict__ Ah, const __nv_bfloat16* __restrict__ Al,
    const __nv_bfloat16* __restrict__ Bh, const __nv_bfloat16* __restrict__ Bl,
    float* __restrict__ C, int M, int N, int K)
{
    extern __shared__ __nv_bfloat16 sm[];
    const int tid  = threadIdx.x;
    const int warp = tid >> 5, lane = tid & 31;
    const int bm = blockIdx.y * 128, bn = blockIdx.x * 128;
    const int wm = (warp >> 2) * 64, wn = (warp & 3) * 32;

    float acc[4][4][4];
#pragma unroll
    for (int i = 0; i < 4; i++)
#pragma unroll
        for (int j = 0; j < 4; j++)
#pragma unroll
            for (int d = 0; d < 4; d++) acc[i][j][d] = 0.0f;

    const int kIters = K >> 5;

    // ---- stage loader (2 chunks per plane per thread) ----
#define LOAD_STAGE(s, k0) do {                                                  \
        __nv_bfloat16* Sah = sm + (s) * STAGE_ELEMS;                            \
        __nv_bfloat16* Sal = Sah + SA_PLANE;                                    \
        __nv_bfloat16* Sbh = Sal + SA_PLANE;                                    \
        __nv_bfloat16* Sbl = Sbh + SB_PLANE;                                    \
        _Pragma("unroll")                                                       \
        for (int cc = 0; cc < 2; cc++) {                                        \
            const int c  = tid + cc * 256;                                      \
            const int ar = c >> 2, ac = c & 3;                                  \
            const size_t ga = (size_t)(bm + ar) * K + (k0) + ac * 8;            \
            cpasync16(Sah + ar * SA_STRIDE + ac * 8, Ah + ga);                  \
            cpasync16(Sal + ar * SA_STRIDE + ac * 8, Al + ga);                  \
            const int br = c >> 4, bc = c & 15;                                 \
            const size_t gb = (size_t)((k0) + br) * N + bn + bc * 8;            \
            cpasync16(Sbh + br * SB_STRIDE + bc * 8, Bh + gb);                  \
            cpasync16(Sbl + br * SB_STRIDE + bc * 8, Bl + gb);                  \
        }                                                                       \
        cp_commit();                                                            \
    } while (0)

    LOAD_STAGE(0, 0);

    for (int it = 0; it < kIters; it++) {
        cp_wait0();
        __syncthreads();
        if (it + 1 < kIters) LOAD_STAGE((it + 1) & 1, (it + 1) * 32);

        const int s = it & 1;
        const __nv_bfloat16* Sah = sm + s * STAGE_ELEMS;
        const __nv_bfloat16* Sal = Sah + SA_PLANE;
        const __nv_bfloat16* Sbh = Sal + SA_PLANE;
        const __nv_bfloat16* Sbl = Sbh + SB_PLANE;

#pragma unroll
        for (int kk = 0; kk < 2; kk++) {
            unsigned ah[4][4], al[4][4];
#pragma unroll
            for (int i = 0; i < 4; i++) {
                const int off = (wm + i * 16 + (lane & 15)) * SA_STRIDE
                              + kk * 16 + (lane >> 4) * 8;
                ldsm4(ah[i], Sah + off);
                ldsm4(al[i], Sal + off);
            }
            unsigned bh[4][2], bl[4][2];
#pragma unroll
            for (int jj = 0; jj < 2; jj++) {
                const int off = (kk * 16 + (lane & 15)) * SB_STRIDE
                              + wn + jj * 16 + (lane >> 4) * 8;
                unsigned t[4];
                ldsm4t(t, Sbh + off);
                bh[2 * jj][0] = t[0]; bh[2 * jj][1] = t[1];
                bh[2 * jj + 1][0] = t[2]; bh[2 * jj + 1][1] = t[3];
                ldsm4t(t, Sbl + off);
                bl[2 * jj][0] = t[0]; bl[2 * jj][1] = t[1];
                bl[2 * jj + 1][0] = t[2]; bl[2 * jj + 1][1] = t[3];
            }
#pragma unroll
            for (int i = 0; i < 4; i++)
#pragma unroll
                for (int j = 0; j < 4; j++) {
                    mma16816(acc[i][j], ah[i], bh[j]);
                    mma16816(acc[i][j], ah[i], bl[j]);
                    mma16816(acc[i][j], al[i], bh[j]);
                }
        }
        __syncthreads();
    }

    // epilogue
#pragma unroll
    for (int i = 0; i < 4; i++)
#pragma unroll
        for (int j = 0; j < 4; j++) {
            const int r = bm + wm + i * 16 + (lane >> 2);
            const int c = bn + wn + j * 8 + (lane & 3) * 2;
            *(float2*)(C + (size_t)r * N + c)       = make_float2(acc[i][j][0], acc[i][j][1]);
            *(float2*)(C + (size_t)(r + 8) * N + c) = make_float2(acc[i][j][2], acc[i][j][3]);
        }
}

// ---------------- RoPE (in place) ------------------------------------------
__global__ void rope_kernel(float* __restrict__ buf, int rowlen, int heads)
{
    const int idx = blockIdx.x * blockDim.x + threadIdx.x;
    const int total = MROWS * heads * 32;
    if (idx >= total) return;
    const int j  = idx & 31;
    const int t1 = idx >> 5;
    const int h  = t1 % heads;
    const int r  = t1 / heads;
    const float tn = (float)(r & (SEQ - 1));

    float* p = buf + (size_t)r * rowlen + h * HDIM;
    const float x1 = p[j];
    const float x2 = p[j + 32];

    const float a1 = tn * g_freqs[j >> 1];
    const float a2 = tn * g_freqs[16 + (j >> 1)];
    float s1, c1, s2, c2;
    sincosf(a1, &s1, &c1);
    sincosf(a2, &s2, &c2);
    p[j]      = x1 * c1 - x2 * s1;
    p[j + 32] = x1 * s2 + x2 * c2;
}

// ---------------- Flash attention (fp32), causal + ALiBi + pad mask -------
#define SWOFF(row, line) (((row) << 6) + ((((line) ^ ((row) >> 2)) & 15) << 2))

__global__ void __launch_bounds__(256, 2) flash_kernel(
    const float* __restrict__ Q, const float* __restrict__ K,
    const float* __restrict__ V, const int* __restrict__ mask,
    float* __restrict__ O)
{
    extern __shared__ float smem[];
    float* Qs = smem;            // 64x64
    float* Ks = smem + 4096;
    float* Vs = smem + 8192;
    float* Ps = smem + 12288;

    const int qt = blockIdx.x, h = blockIdx.y, b = blockIdx.z;
    const int kvh = h >> 2;
    const int tid = threadIdx.x;
    const int tx = tid & 15, ty = tid >> 4;
    const int r0 = ty * 4, c0 = tx * 4;
    const float scale = 0.125f;
    const float slope = exp2f(-0.25f * (float)(h + 1));

#pragma unroll
    for (int i = tid; i < 1024; i += 256) {
        const int row = i >> 4, l = i & 15;
        const float4 v = *(const float4*)(
            Q + (size_t)(b * SEQ + qt * 64 + row) * (NHEADS * HDIM) + h * HDIM + l * 4);
        *(float4*)(Qs + SWOFF(row, l)) = v;
    }

    float m_i[4], l_i[4], acc[4][4];
#pragma unroll
    for (int i = 0; i < 4; i++) {
        m_i[i] = -1e30f; l_i[i] = 0.0f;
#pragma unroll
        for (int j = 0; j < 4; j++) acc[i][j] = 0.0f;
    }

    for (int kt = 0; kt <= qt; kt++) {
        __syncthreads();
#pragma unroll
        for (int i = tid; i < 1024; i += 256) {
            const int row = i >> 4, l = i & 15;
            const size_t g = (size_t)(b * SEQ + kt * 64 + row) * (KVHEADS * HDIM) + kvh * HDIM + l * 4;
            const int off = SWOFF(row, l);
            *(float4*)(Ks + off) = *(const float4*)(K + g);
            *(float4*)(Vs + off) = *(const float4*)(V + g);
        }
        __syncthreads();

        float s[4][4];
#pragma unroll
        for (int i = 0; i < 4; i++)
#pragma unroll
            for (int j = 0; j < 4; j++) s[i][j] = 0.0f;

#pragma unroll
        for (int dl = 0; dl < 16; dl++) {
            float4 qv[4], kv[4];
#pragma unroll
            for (int i = 0; i < 4; i++) qv[i] = *(const float4*)(Qs + ((r0 + i) << 6) + (((dl ^ ty) & 15) << 2));
#pragma unroll
            for (int j = 0; j < 4; j++) kv[j] = *(const float4*)(Ks + ((c0 + j) << 6) + (((dl ^ tx) & 15) << 2));
#pragma unroll
            for (int i = 0; i < 4; i++) {
                const float* qa = (const float*)&qv[i];
#pragma unroll
                for (int j = 0; j < 4; j++) {
                    const float* ka = (const float*)&kv[j];
                    s[i][j] += qa[0] * ka[0] + qa[1] * ka[1] + qa[2] * ka[2] + qa[3] * ka[3];
                }
            }
        }

        const int qg0 = qt * 64 + r0;
        const int kg0 = kt * 64 + c0;
        int pm[4];
#pragma unroll
        for (int j = 0; j < 4; j++) pm[j] = __ldg(mask + b * SEQ + kg0 + j);
#pragma unroll
        for (int i = 0; i < 4; i++)
#pragma unroll
            for (int j = 0; j < 4; j++) {
                const int kg = kg0 + j;
                float v = s[i][j] * scale + slope * (float)kg;
                if (kg > qg0 + i || pm[j] == 0) v = -1e30f;
                s[i][j] = v;
            }

#pragma unroll
        for (int i = 0; i < 4; i++) {
            float mx = fmaxf(fmaxf(s[i][0], s[i][1]), fmaxf(s[i][2], s[i][3]));
            mx = fmaxf(mx, __shfl_xor_sync(0xffffffffu, mx, 1));
            mx = fmaxf(mx, __shfl_xor_sync(0xffffffffu, mx, 2));
            mx = fmaxf(mx, __shfl_xor_sync(0xffffffffu, mx, 4));
            mx = fmaxf(mx, __shfl_xor_sync(0xffffffffu, mx, 8));
            const float mnew = fmaxf(m_i[i], mx);
            const float corr = __expf(m_i[i] - mnew);
            float ps = 0.0f;
#pragma unroll
            for (int j = 0; j < 4; j++) { const float p = __expf(s[i][j] - mnew); s[i][j] = p; ps += p; }
            ps += __shfl_xor_sync(0xffffffffu, ps, 1);
            ps += __shfl_xor_sync(0xffffffffu, ps, 2);
            ps += __shfl_xor_sync(0xffffffffu, ps, 4);
            ps += __shfl_xor_sync(0xffffffffu, ps, 8);
            l_i[i] = l_i[i] * corr + ps;
            m_i[i] = mnew;
#pragma unroll
            for (int j = 0; j < 4; j++) acc[i][j] *= corr;
            *(float4*)(Ps + ((r0 + i) << 6) + (((tx ^ ty) & 15) << 2)) =
                make_float4(s[i][0], s[i][1], s[i][2], s[i][3]);
        }
        __syncthreads();

#pragma unroll
        for (int cl = 0; cl < 16; cl++) {
            float4 pvv[4], vvv[4];
#pragma unroll
            for (int i = 0; i < 4; i++) pvv[i] = *(const float4*)(Ps + ((r0 + i) << 6) + (((cl ^ ty) & 15) << 2));
#pragma unroll
            for (int k = 0; k < 4; k++) vvv[k] = *(const float4*)(Vs + ((cl * 4 + k) << 6) + (((tx ^ cl) & 15) << 2));
#pragma unroll
            for (int i = 0; i < 4; i++) {
                const float* pp = (const float*)&pvv[i];
#pragma unroll
                for (int k = 0; k < 4; k++) {
                    const float  pk = pp[k];
                    const float* vk = (const float*)&vvv[k];
                    acc[i][0] += pk * vk[0];
                    acc[i][1] += pk * vk[1];
                    acc[i][2] += pk * vk[2];
                    acc[i][3] += pk * vk[3];
                }
            }
        }
    }

#pragma unroll
    for (int i = 0; i < 4; i++) {
        const float inv = 1.0f / l_i[i];
        float4 r = make_float4(acc[i][0] * inv, acc[i][1] * inv, acc[i][2] * inv, acc[i][3] * inv);
        *(float4*)(O + (size_t)(b * SEQ + qt * 64 + r0 + i) * (NHEADS * HDIM) + h * HDIM + c0) = r;
    }
}

// ---------------- host launcher -------------------------------------------
extern "C" void kernel_launch(void* const* d_in, const int* in_sizes, int n_in,
                              void* d_out, int out_size)
{
    const float* x    = (const float*)d_in[0];
    const int*   mask = (const int*)  d_in[1];
    const float* Wq   = (const float*)d_in[2];
    const float* Wk   = (const float*)d_in[3];
    const float* Wv   = (const float*)d_in[4];
    const float* Wo   = (const float*)d_in[5];
    float* out = (float*)d_out;

    void *pQ, *pK, *pV, *pO;
    void *pxh, *pxl, *pWqh, *pWql, *pWkh, *pWkl, *pWvh, *pWvl, *pWoh, *pWol, *pOh, *pOl;
    cudaGetSymbolAddress(&pQ, g_Q);  cudaGetSymbolAddress(&pK, g_K);
    cudaGetSymbolAddress(&pV, g_V);  cudaGetSymbolAddress(&pO, g_O);
    cudaGetSymbolAddress(&pxh, g_xh);  cudaGetSymbolAddress(&pxl, g_xl);
    cudaGetSymbolAddress(&pWqh, g_Wqh); cudaGetSymbolAddress(&pWql, g_Wql);
    cudaGetSymbolAddress(&pWkh, g_Wkh); cudaGetSymbolAddress(&pWkl, g_Wkl);
    cudaGetSymbolAddress(&pWvh, g_Wvh); cudaGetSymbolAddress(&pWvl, g_Wvl);
    cudaGetSymbolAddress(&pWoh, g_Woh); cudaGetSymbolAddress(&pWol, g_Wol);
    cudaGetSymbolAddress(&pOh, g_Oh);   cudaGetSymbolAddress(&pOl, g_Ol);

    init_freqs_kernel<<<1, 32>>>();

    // split fp32 operands into (hi, lo) bf16 planes
    split_kernel<<<(MROWS * DMODEL / 4) / 256, 256>>>(x,  (__nv_bfloat16*)pxh, (__nv_bfloat16*)pxl, MROWS * DMODEL / 4);
    split_kernel<<<(DMODEL * 2048 / 4) / 256, 256>>>(Wq, (__nv_bfloat16*)pWqh, (__nv_bfloat16*)pWql, DMODEL * 2048 / 4);
    split_kernel<<<(DMODEL * 512  / 4) / 256, 256>>>(Wk, (__nv_bfloat16*)pWkh, (__nv_bfloat16*)pWkl, DMODEL * 512 / 4);
    split_kernel<<<(DMODEL * 512  / 4) / 256, 256>>>(Wv, (__nv_bfloat16*)pWvh, (__nv_bfloat16*)pWvl, DMODEL * 512 / 4);
    split_kernel<<<(2048 * DMODEL / 4) / 256, 256>>>(Wo, (__nv_bfloat16*)pWoh, (__nv_bfloat16*)pWol, 2048 * DMODEL / 4);

    cudaFuncSetAttribute(gemm_bf16x3, cudaFuncAttributeMaxDynamicSharedMemorySize, GEMM_SMEM);

    // QKV projections (tensor cores)
    gemm_bf16x3<<<dim3(2048 / 128, MROWS / 128), 256, GEMM_SMEM>>>(
        (const __nv_bfloat16*)pxh, (const __nv_bfloat16*)pxl,
        (const __nv_bfloat16*)pWqh, (const __nv_bfloat16*)pWql,
        (float*)pQ, MROWS, 2048, DMODEL);
    gemm_bf16x3<<<dim3(512 / 128, MROWS / 128), 256, GEMM_SMEM>>>(
        (const __nv_bfloat16*)pxh, (const __nv_bfloat16*)pxl,
        (const __nv_bfloat16*)pWkh, (const __nv_bfloat16*)pWkl,
        (float*)pK, MROWS, 512, DMODEL);
    gemm_bf16x3<<<dim3(512 / 128, MROWS / 128), 256, GEMM_SMEM>>>(
        (const __nv_bfloat16*)pxh, (const __nv_bfloat16*)pxl,
        (const __nv_bfloat16*)pWvh, (const __nv_bfloat16*)pWvl,
        (float*)pV, MROWS, 512, DMODEL);

    // RoPE
    rope_kernel<<<(MROWS * NHEADS  * 32) / 256, 256>>>((float*)pQ, NHEADS  * HDIM, NHEADS);
    rope_kernel<<<(MROWS * KVHEADS * 32) / 256, 256>>>((float*)pK, KVHEADS * HDIM, KVHEADS);

    // Flash attention (fp32)
    cudaFuncSetAttribute(flash_kernel, cudaFuncAttributeMaxDynamicSharedMemorySize, 65536);
    flash_kernel<<<dim3(SEQ / 64, NHEADS, BATCH), 256, 65536>>>(
        (const float*)pQ, (const float*)pK, (const float*)pV, mask, (float*)pO);

    // Output projection (tensor cores)
    split_kernel<<<(MROWS * 2048 / 4) / 256, 256>>>((const float*)pO, (__nv_bfloat16*)pOh, (__nv_bfloat16*)pOl, MROWS * 2048 / 4);
    gemm_bf16x3<<<dim3(2048 / 128, MROWS / 128), 256, GEMM_SMEM>>>(
        (const __nv_bfloat16*)pOh, (const __nv_bfloat16*)pOl,
        (const __nv_bfloat16*)pWoh, (const __nv_bfloat16*)pWol,
        out, MROWS, 2048, DMODEL);
}

// round 6
// speedup vs baseline: 2.9015x; 1.5832x over previous
#include <cuda_runtime.h>
#include <cuda_bf16.h>
#include <math.h>

#define BATCH   2
#define SEQ     2048
#define DMODEL  2048
#define NHEADS  32
#define HDIM    64
#define KVHEADS 8
#define MROWS   (BATCH*SEQ)          // 4096

// ---------------- scratch (device globals; no allocation allowed) ----------
__device__ float g_Q[MROWS * NHEADS * HDIM];    // 4096 x 2048
__device__ float g_K[MROWS * KVHEADS * HDIM];   // 4096 x 512
__device__ float g_V[MROWS * KVHEADS * HDIM];   // 4096 x 512
__device__ float g_freqs[32];

// split-bf16 planes
__device__ __nv_bfloat16 g_xh [MROWS * DMODEL];
__device__ __nv_bfloat16 g_xl [MROWS * DMODEL];
__device__ __nv_bfloat16 g_Wqh[DMODEL * 2048];
__device__ __nv_bfloat16 g_Wql[DMODEL * 2048];
__device__ __nv_bfloat16 g_Wkh[DMODEL * 512];
__device__ __nv_bfloat16 g_Wkl[DMODEL * 512];
__device__ __nv_bfloat16 g_Wvh[DMODEL * 512];
__device__ __nv_bfloat16 g_Wvl[DMODEL * 512];
__device__ __nv_bfloat16 g_Woh[2048 * DMODEL];
__device__ __nv_bfloat16 g_Wol[2048 * DMODEL];
__device__ __nv_bfloat16 g_Qh [MROWS * 2048];
__device__ __nv_bfloat16 g_Ql [MROWS * 2048];
__device__ __nv_bfloat16 g_Kh [MROWS * 512];
__device__ __nv_bfloat16 g_Kl [MROWS * 512];
__device__ __nv_bfloat16 g_Vh [MROWS * 512];
__device__ __nv_bfloat16 g_Vl [MROWS * 512];
__device__ __nv_bfloat16 g_Oh [MROWS * 2048];
__device__ __nv_bfloat16 g_Ol [MROWS * 2048];

// ---------------- RoPE frequency table -------------------------------------
__global__ void init_freqs_kernel() {
    int i = threadIdx.x;  // 32 threads
    g_freqs[i] = (float)exp2(-(double)i * (13.287712379549449 / 32.0));
}

// ---------------- fp32 -> (hi, lo) bf16 split -------------------------------
__global__ void __launch_bounds__(256) split_kernel(
    const float* __restrict__ src, __nv_bfloat16* __restrict__ hi,
    __nv_bfloat16* __restrict__ lo, int n4)
{
    const int i = blockIdx.x * blockDim.x + threadIdx.x;
    if (i >= n4) return;
    const float4 f = ((const float4*)src)[i];
    __nv_bfloat16 h[4], l[4];
    const float fv[4] = {f.x, f.y, f.z, f.w};
#pragma unroll
    for (int k = 0; k < 4; k++) {
        h[k] = __float2bfloat16(fv[k]);
        l[k] = __float2bfloat16(fv[k] - __bfloat162float(h[k]));
    }
    *(uint2*)(hi + 4 * (size_t)i) = *(uint2*)h;
    *(uint2*)(lo + 4 * (size_t)i) = *(uint2*)l;
}

// ---------------- PTX helpers ----------------------------------------------
__device__ __forceinline__ void cpasync16(void* s, const void* g) {
    unsigned sa = (unsigned)__cvta_generic_to_shared(s);
    asm volatile("cp.async.cg.shared.global [%0], [%1], 16;\n" :: "r"(sa), "l"(g));
}
__device__ __forceinline__ void cp_commit() {
    asm volatile("cp.async.commit_group;\n" ::: "memory");
}
__device__ __forceinline__ void cp_wait0() {
    asm volatile("cp.async.wait_group 0;\n" ::: "memory");
}
__device__ __forceinline__ void ldsm4(unsigned* r, const void* p) {
    unsigned a = (unsigned)__cvta_generic_to_shared(p);
    asm volatile("ldmatrix.sync.aligned.m8n8.x4.shared.b16 {%0,%1,%2,%3}, [%4];"
                 : "=r"(r[0]), "=r"(r[1]), "=r"(r[2]), "=r"(r[3]) : "r"(a));
}
__device__ __forceinline__ void ldsm4t(unsigned* r, const void* p) {
    unsigned a = (unsigned)__cvta_generic_to_shared(p);
    asm volatile("ldmatrix.sync.aligned.m8n8.x4.trans.shared.b16 {%0,%1,%2,%3}, [%4];"
                 : "=r"(r[0]), "=r"(r[1]), "=r"(r[2]), "=r"(r[3]) : "r"(a));
}
__device__ __forceinline__ void mma16816(float* d, const unsigned* a, const unsigned* b) {
    asm volatile("mma.sync.aligned.m16n8k16.row.col.f32.bf16.bf16.f32 "
                 "{%0,%1,%2,%3},{%4,%5,%6,%7},{%8,%9},{%0,%1,%2,%3};"
                 : "+f"(d[0]), "+f"(d[1]), "+f"(d[2]), "+f"(d[3])
                 : "r"(a[0]), "r"(a[1]), "r"(a[2]), "r"(a[3]), "r"(b[0]), "r"(b[1]));
}
__device__ __forceinline__ unsigned swz(unsigned o) { return o ^ ((o >> 3) & 0x70); }

__device__ __forceinline__ void f2bf_split(float x, float y, unsigned& hi, unsigned& lo) {
    __nv_bfloat162 h = __floats2bfloat162_rn(x, y);
    float rx = x - __bfloat162float(h.x);
    float ry = y - __bfloat162float(h.y);
    __nv_bfloat162 l = __floats2bfloat162_rn(rx, ry);
    hi = *(unsigned*)&h; lo = *(unsigned*)&l;
}

// ---------------- split-bf16 3-product tensor-core GEMM ---------------------
#define SA_STRIDE 56
#define SB_STRIDE 136
#define SA_PLANE  (128 * SA_STRIDE)
#define SB_PLANE  (32 * SB_STRIDE)
#define STAGE_ELEMS (2 * SA_PLANE + 2 * SB_PLANE)
#define GEMM_SMEM (2 * STAGE_ELEMS * 2)

__global__ void __launch_bounds__(256, 1) gemm_bf16x3(
    const __nv_bfloat16* __restrict__ Ah, const __nv_bfloat16* __restrict__ Al,
    const __nv_bfloat16* __restrict__ Bh, const __nv_bfloat16* __restrict__ Bl,
    float* __restrict__ C, int M, int N, int K)
{
    extern __shared__ __nv_bfloat16 sm[];
    const int tid  = threadIdx.x;
    const int warp = tid >> 5, lane = tid & 31;
    const int bm = blockIdx.y * 128, bn = blockIdx.x * 128;
    const int wm = (warp >> 2) * 64, wn = (warp & 3) * 32;

    float acc[4][4][4];
#pragma unroll
    for (int i = 0; i < 4; i++)
#pragma unroll
        for (int j = 0; j < 4; j++)
#pragma unroll
            for (int d = 0; d < 4; d++) acc[i][j][d] = 0.0f;

    const int kIters = K >> 5;

#define LOAD_STAGE(s, k0) do {                                                  \
        __nv_bfloat16* Sah = sm + (s) * STAGE_ELEMS;                            \
        __nv_bfloat16* Sal = Sah + SA_PLANE;                                    \
        __nv_bfloat16* Sbh = Sal + SA_PLANE;                                    \
        __nv_bfloat16* Sbl = Sbh + SB_PLANE;                                    \
        _Pragma("unroll")                                                       \
        for (int cc = 0; cc < 2; cc++) {                                        \
            const int c  = tid + cc * 256;                                      \
            const int ar = c >> 2, ac = c & 3;                                  \
            const size_t ga = (size_t)(bm + ar) * K + (k0) + ac * 8;            \
            cpasync16(Sah + ar * SA_STRIDE + ac * 8, Ah + ga);                  \
            cpasync16(Sal + ar * SA_STRIDE + ac * 8, Al + ga);                  \
            const int br = c >> 4, bc = c & 15;                                 \
            const size_t gb = (size_t)((k0) + br) * N + bn + bc * 8;            \
            cpasync16(Sbh + br * SB_STRIDE + bc * 8, Bh + gb);                  \
            cpasync16(Sbl + br * SB_STRIDE + bc * 8, Bl + gb);                  \
        }                                                                       \
        cp_commit();                                                            \
    } while (0)

    LOAD_STAGE(0, 0);

    for (int it = 0; it < kIters; it++) {
        cp_wait0();
        __syncthreads();
        if (it + 1 < kIters) LOAD_STAGE((it + 1) & 1, (it + 1) * 32);

        const int s = it & 1;
        const __nv_bfloat16* Sah = sm + s * STAGE_ELEMS;
        const __nv_bfloat16* Sal = Sah + SA_PLANE;
        const __nv_bfloat16* Sbh = Sal + SA_PLANE;
        const __nv_bfloat16* Sbl = Sbh + SB_PLANE;

#pragma unroll
        for (int kk = 0; kk < 2; kk++) {
            unsigned ah[4][4], al[4][4];
#pragma unroll
            for (int i = 0; i < 4; i++) {
                const int off = (wm + i * 16 + (lane & 15)) * SA_STRIDE
                              + kk * 16 + (lane >> 4) * 8;
                ldsm4(ah[i], Sah + off);
                ldsm4(al[i], Sal + off);
            }
            unsigned bh[4][2], bl[4][2];
#pragma unroll
            for (int jj = 0; jj < 2; jj++) {
                const int off = (kk * 16 + (lane & 15)) * SB_STRIDE
                              + wn + jj * 16 + (lane >> 4) * 8;
                unsigned t[4];
                ldsm4t(t, Sbh + off);
                bh[2 * jj][0] = t[0]; bh[2 * jj][1] = t[1];
                bh[2 * jj + 1][0] = t[2]; bh[2 * jj + 1][1] = t[3];
                ldsm4t(t, Sbl + off);
                bl[2 * jj][0] = t[0]; bl[2 * jj][1] = t[1];
                bl[2 * jj + 1][0] = t[2]; bl[2 * jj + 1][1] = t[3];
            }
#pragma unroll
            for (int i = 0; i < 4; i++)
#pragma unroll
                for (int j = 0; j < 4; j++) {
                    mma16816(acc[i][j], ah[i], bh[j]);
                    mma16816(acc[i][j], ah[i], bl[j]);
                    mma16816(acc[i][j], al[i], bh[j]);
                }
        }
        __syncthreads();
    }

#pragma unroll
    for (int i = 0; i < 4; i++)
#pragma unroll
        for (int j = 0; j < 4; j++) {
            const int r = bm + wm + i * 16 + (lane >> 2);
            const int c = bn + wn + j * 8 + (lane & 3) * 2;
            *(float2*)(C + (size_t)r * N + c)       = make_float2(acc[i][j][0], acc[i][j][1]);
            *(float2*)(C + (size_t)(r + 8) * N + c) = make_float2(acc[i][j][2], acc[i][j][3]);
        }
}

// ---------------- RoPE (in place) ------------------------------------------
__global__ void rope_kernel(float* __restrict__ buf, int rowlen, int heads)
{
    const int idx = blockIdx.x * blockDim.x + threadIdx.x;
    const int total = MROWS * heads * 32;
    if (idx >= total) return;
    const int j  = idx & 31;
    const int t1 = idx >> 5;
    const int h  = t1 % heads;
    const int r  = t1 / heads;
    const float tn = (float)(r & (SEQ - 1));

    float* p = buf + (size_t)r * rowlen + h * HDIM;
    const float x1 = p[j];
    const float x2 = p[j + 32];

    const float a1 = tn * g_freqs[j >> 1];
    const float a2 = tn * g_freqs[16 + (j >> 1)];
    float s1, c1, s2, c2;
    sincosf(a1, &s1, &c1);
    sincosf(a2, &s2, &c2);
    p[j]      = x1 * c1 - x2 * s1;
    p[j + 32] = x1 * s2 + x2 * c2;
}

// ---------------- Flash attention on tensor cores (split-bf16) -------------
// Block: 128 threads = 4 warps; q-tile 64 (16 rows/warp); key tiles of 64.
// smem: Qh,Ql,Kh,Kl,Vh,Vl 8KB tiles (64x128B rows, SW128 swizzle) + bias.
#define FL_SMEM (6 * 8192 + 256)

__global__ void __launch_bounds__(128, 2) flash_mma_kernel(
    const __nv_bfloat16* __restrict__ Qh, const __nv_bfloat16* __restrict__ Ql,
    const __nv_bfloat16* __restrict__ Kh, const __nv_bfloat16* __restrict__ Kl,
    const __nv_bfloat16* __restrict__ Vh, const __nv_bfloat16* __restrict__ Vl,
    const int* __restrict__ mask,
    __nv_bfloat16* __restrict__ Oh, __nv_bfloat16* __restrict__ Ol)
{
    extern __shared__ char smc[];
    char* Qsh = smc;
    char* Qsl = smc + 8192;
    char* Ksh = smc + 16384;
    char* Ksl = smc + 24576;
    char* Vsh = smc + 32768;
    char* Vsl = smc + 40960;
    float* bias = (float*)(smc + 49152);

    const int qt = (gridDim.x - 1) - blockIdx.x;   // long blocks first
    const int h = blockIdx.y, b = blockIdx.z;
    const int kvh = h >> 2;
    const int tid = threadIdx.x, warp = tid >> 5, lane = tid & 31;
    const int g = lane >> 2, t2 = (lane & 3) * 2;
    const float scale = 0.125f;
    const float slope = exp2f(-0.25f * (float)(h + 1));

    // ---- load Q tile (64x64 bf16 x2 planes) and build A fragments ----
    {
        const size_t base = (size_t)(b * SEQ + qt * 64) * 2048 + h * 64;
#pragma unroll
        for (int cc = 0; cc < 4; cc++) {
            const int c = tid + cc * 128;
            const int row = c >> 3, k8 = c & 7;
            const size_t gp = base + (size_t)row * 2048 + k8 * 8;
            const unsigned so = swz(row * 128 + k8 * 16);
            cpasync16(Qsh + so, Qh + gp);
            cpasync16(Qsl + so, Ql + gp);
        }
        cp_commit(); cp_wait0();
        __syncthreads();
    }
    unsigned qh[4][4], ql[4][4];
#pragma unroll
    for (int kc = 0; kc < 4; kc++) {
        const unsigned ad = swz((warp * 16 + (lane & 15)) * 128 + kc * 32 + (lane >> 4) * 16);
        ldsm4(qh[kc], Qsh + ad);
        ldsm4(ql[kc], Qsl + ad);
    }

    float o[8][4];
#pragma unroll
    for (int j = 0; j < 8; j++)
#pragma unroll
        for (int d = 0; d < 4; d++) o[j][d] = 0.0f;
    float m0 = -1e30f, m1 = -1e30f, l0 = 0.0f, l1 = 0.0f;
    const int qrow0 = qt * 64 + warp * 16 + g;

    for (int kt = 0; kt <= qt; kt++) {
        __syncthreads();
        {
            const size_t kbase = (size_t)(b * SEQ + kt * 64) * 512 + kvh * 64;
#pragma unroll
            for (int cc = 0; cc < 4; cc++) {
                const int c = tid + cc * 128;
                const int row = c >> 3, k8 = c & 7;
                const size_t gp = kbase + (size_t)row * 512 + k8 * 8;
                const unsigned so = swz(row * 128 + k8 * 16);
                cpasync16(Ksh + so, Kh + gp);
                cpasync16(Ksl + so, Kl + gp);
                cpasync16(Vsh + so, Vh + gp);
                cpasync16(Vsl + so, Vl + gp);
            }
        }
        if (tid < 64) bias[tid] = mask[b * SEQ + kt * 64 + tid] ? 0.0f : -1e30f;
        cp_commit(); cp_wait0();
        __syncthreads();

        // ---- S = Q K^T (3 products) ----
        float s[8][4];
#pragma unroll
        for (int j = 0; j < 8; j++)
#pragma unroll
            for (int d = 0; d < 4; d++) s[j][d] = 0.0f;

#pragma unroll
        for (int kc = 0; kc < 4; kc++)
#pragma unroll
            for (int jj = 0; jj < 4; jj++) {
                const unsigned ad = swz((jj * 16 + (lane & 15)) * 128 + kc * 32 + (lane >> 4) * 16);
                unsigned tt[4], uu[4];
                ldsm4(tt, Ksh + ad);
                ldsm4(uu, Ksl + ad);
                unsigned bh[2], bl[2];
                bh[0] = tt[0]; bh[1] = tt[2]; bl[0] = uu[0]; bl[1] = uu[2];
                mma16816(s[2 * jj], qh[kc], bh);
                mma16816(s[2 * jj], ql[kc], bh);
                mma16816(s[2 * jj], qh[kc], bl);
                bh[0] = tt[1]; bh[1] = tt[3]; bl[0] = uu[1]; bl[1] = uu[3];
                mma16816(s[2 * jj + 1], qh[kc], bh);
                mma16816(s[2 * jj + 1], ql[kc], bh);
                mma16816(s[2 * jj + 1], qh[kc], bl);
            }

        // ---- scale + ALiBi + causal + pad ----
#pragma unroll
        for (int j = 0; j < 8; j++) {
            const int kg = kt * 64 + j * 8 + t2;
            const float b0 = bias[j * 8 + t2];
            const float b1 = bias[j * 8 + t2 + 1];
            const float al0 = fmaf(slope, (float)kg, b0);
            const float al1 = fmaf(slope, (float)(kg + 1), b1);
            float v0 = fmaf(s[j][0], scale, al0);
            float v1 = fmaf(s[j][1], scale, al1);
            float v2 = fmaf(s[j][2], scale, al0);
            float v3 = fmaf(s[j][3], scale, al1);
            if (kg     > qrow0)     v0 = -1e30f;
            if (kg + 1 > qrow0)     v1 = -1e30f;
            if (kg     > qrow0 + 8) v2 = -1e30f;
            if (kg + 1 > qrow0 + 8) v3 = -1e30f;
            s[j][0] = v0; s[j][1] = v1; s[j][2] = v2; s[j][3] = v3;
        }

        // ---- online softmax ----
        float mx0 = -1e30f, mx1 = -1e30f;
#pragma unroll
        for (int j = 0; j < 8; j++) {
            mx0 = fmaxf(mx0, fmaxf(s[j][0], s[j][1]));
            mx1 = fmaxf(mx1, fmaxf(s[j][2], s[j][3]));
        }
        mx0 = fmaxf(mx0, __shfl_xor_sync(0xffffffffu, mx0, 1));
        mx0 = fmaxf(mx0, __shfl_xor_sync(0xffffffffu, mx0, 2));
        mx1 = fmaxf(mx1, __shfl_xor_sync(0xffffffffu, mx1, 1));
        mx1 = fmaxf(mx1, __shfl_xor_sync(0xffffffffu, mx1, 2));
        const float mn0 = fmaxf(m0, mx0), mn1 = fmaxf(m1, mx1);
        const float cr0 = __expf(m0 - mn0), cr1 = __expf(m1 - mn1);
        float ps0 = 0.0f, ps1 = 0.0f;
#pragma unroll
        for (int j = 0; j < 8; j++) {
            s[j][0] = __expf(s[j][0] - mn0);
            s[j][1] = __expf(s[j][1] - mn0);
            s[j][2] = __expf(s[j][2] - mn1);
            s[j][3] = __expf(s[j][3] - mn1);
            ps0 += s[j][0] + s[j][1];
            ps1 += s[j][2] + s[j][3];
        }
        ps0 += __shfl_xor_sync(0xffffffffu, ps0, 1);
        ps0 += __shfl_xor_sync(0xffffffffu, ps0, 2);
        ps1 += __shfl_xor_sync(0xffffffffu, ps1, 1);
        ps1 += __shfl_xor_sync(0xffffffffu, ps1, 2);
        l0 = l0 * cr0 + ps0; m0 = mn0;
        l1 = l1 * cr1 + ps1; m1 = mn1;
#pragma unroll
        for (int j = 0; j < 8; j++) {
            o[j][0] *= cr0; o[j][1] *= cr0;
            o[j][2] *= cr1; o[j][3] *= cr1;
        }

        // ---- O += P V (3 products), P from S fragments ----
#pragma unroll
        for (int kc = 0; kc < 4; kc++) {
            unsigned ph[4], pl[4];
            f2bf_split(s[2 * kc][0],     s[2 * kc][1],     ph[0], pl[0]);
            f2bf_split(s[2 * kc][2],     s[2 * kc][3],     ph[1], pl[1]);
            f2bf_split(s[2 * kc + 1][0], s[2 * kc + 1][1], ph[2], pl[2]);
            f2bf_split(s[2 * kc + 1][2], s[2 * kc + 1][3], ph[3], pl[3]);
#pragma unroll
            for (int jj = 0; jj < 4; jj++) {
                const unsigned ad = swz((kc * 16 + (lane & 15)) * 128 + jj * 32 + (lane >> 4) * 16);
                unsigned tt[4], uu[4];
                ldsm4t(tt, Vsh + ad);
                ldsm4t(uu, Vsl + ad);
                unsigned bh[2], bl[2];
                bh[0] = tt[0]; bh[1] = tt[1]; bl[0] = uu[0]; bl[1] = uu[1];
                mma16816(o[2 * jj], ph, bh);
                mma16816(o[2 * jj], pl, bh);
                mma16816(o[2 * jj], ph, bl);
                bh[0] = tt[2]; bh[1] = tt[3]; bl[0] = uu[2]; bl[1] = uu[3];
                mma16816(o[2 * jj + 1], ph, bh);
                mma16816(o[2 * jj + 1], pl, bh);
                mma16816(o[2 * jj + 1], ph, bl);
            }
        }
    }

    // ---- epilogue: normalize, split to bf16 hi/lo, store ----
    const float inv0 = 1.0f / l0, inv1 = 1.0f / l1;
#pragma unroll
    for (int j = 0; j < 8; j++) {
        const size_t p0 = (size_t)(b * SEQ + qrow0) * 2048 + h * 64 + j * 8 + t2;
        unsigned hh, ll;
        f2bf_split(o[j][0] * inv0, o[j][1] * inv0, hh, ll);
        *(unsigned*)(Oh + p0) = hh;
        *(unsigned*)(Ol + p0) = ll;
        f2bf_split(o[j][2] * inv1, o[j][3] * inv1, hh, ll);
        *(unsigned*)(Oh + p0 + 8 * 2048) = hh;
        *(unsigned*)(Ol + p0 + 8 * 2048) = ll;
    }
}

// ---------------- host launcher -------------------------------------------
extern "C" void kernel_launch(void* const* d_in, const int* in_sizes, int n_in,
                              void* d_out, int out_size)
{
    const float* x    = (const float*)d_in[0];
    const int*   mask = (const int*)  d_in[1];
    const float* Wq   = (const float*)d_in[2];
    const float* Wk   = (const float*)d_in[3];
    const float* Wv   = (const float*)d_in[4];
    const float* Wo   = (const float*)d_in[5];
    float* out = (float*)d_out;

    void *pQ, *pK, *pV;
    void *pxh, *pxl, *pWqh, *pWql, *pWkh, *pWkl, *pWvh, *pWvl, *pWoh, *pWol;
    void *pQh, *pQl, *pKh, *pKl, *pVh, *pVl, *pOh, *pOl;
    cudaGetSymbolAddress(&pQ, g_Q);  cudaGetSymbolAddress(&pK, g_K);
    cudaGetSymbolAddress(&pV, g_V);
    cudaGetSymbolAddress(&pxh, g_xh);  cudaGetSymbolAddress(&pxl, g_xl);
    cudaGetSymbolAddress(&pWqh, g_Wqh); cudaGetSymbolAddress(&pWql, g_Wql);
    cudaGetSymbolAddress(&pWkh, g_Wkh); cudaGetSymbolAddress(&pWkl, g_Wkl);
    cudaGetSymbolAddress(&pWvh, g_Wvh); cudaGetSymbolAddress(&pWvl, g_Wvl);
    cudaGetSymbolAddress(&pWoh, g_Woh); cudaGetSymbolAddress(&pWol, g_Wol);
    cudaGetSymbolAddress(&pQh, g_Qh);   cudaGetSymbolAddress(&pQl, g_Ql);
    cudaGetSymbolAddress(&pKh, g_Kh);   cudaGetSymbolAddress(&pKl, g_Kl);
    cudaGetSymbolAddress(&pVh, g_Vh);   cudaGetSymbolAddress(&pVl, g_Vl);
    cudaGetSymbolAddress(&pOh, g_Oh);   cudaGetSymbolAddress(&pOl, g_Ol);

    init_freqs_kernel<<<1, 32>>>();

    // split fp32 operands into (hi, lo) bf16 planes
    split_kernel<<<(MROWS * DMODEL / 4) / 256, 256>>>(x,  (__nv_bfloat16*)pxh, (__nv_bfloat16*)pxl, MROWS * DMODEL / 4);
    split_kernel<<<(DMODEL * 2048 / 4) / 256, 256>>>(Wq, (__nv_bfloat16*)pWqh, (__nv_bfloat16*)pWql, DMODEL * 2048 / 4);
    split_kernel<<<(DMODEL * 512  / 4) / 256, 256>>>(Wk, (__nv_bfloat16*)pWkh, (__nv_bfloat16*)pWkl, DMODEL * 512 / 4);
    split_kernel<<<(DMODEL * 512  / 4) / 256, 256>>>(Wv, (__nv_bfloat16*)pWvh, (__nv_bfloat16*)pWvl, DMODEL * 512 / 4);
    split_kernel<<<(2048 * DMODEL / 4) / 256, 256>>>(Wo, (__nv_bfloat16*)pWoh, (__nv_bfloat16*)pWol, 2048 * DMODEL / 4);

    cudaFuncSetAttribute(gemm_bf16x3, cudaFuncAttributeMaxDynamicSharedMemorySize, GEMM_SMEM);

    // QKV projections (tensor cores)
    gemm_bf16x3<<<dim3(2048 / 128, MROWS / 128), 256, GEMM_SMEM>>>(
        (const __nv_bfloat16*)pxh, (const __nv_bfloat16*)pxl,
        (const __nv_bfloat16*)pWqh, (const __nv_bfloat16*)pWql,
        (float*)pQ, MROWS, 2048, DMODEL);
    gemm_bf16x3<<<dim3(512 / 128, MROWS / 128), 256, GEMM_SMEM>>>(
        (const __nv_bfloat16*)pxh, (const __nv_bfloat16*)pxl,
        (const __nv_bfloat16*)pWkh, (const __nv_bfloat16*)pWkl,
        (float*)pK, MROWS, 512, DMODEL);
    gemm_bf16x3<<<dim3(512 / 128, MROWS / 128), 256, GEMM_SMEM>>>(
        (const __nv_bfloat16*)pxh, (const __nv_bfloat16*)pxl,
        (const __nv_bfloat16*)pWvh, (const __nv_bfloat16*)pWvl,
        (float*)pV, MROWS, 512, DMODEL);

    // RoPE
    rope_kernel<<<(MROWS * NHEADS  * 32) / 256, 256>>>((float*)pQ, NHEADS  * HDIM, NHEADS);
    rope_kernel<<<(MROWS * KVHEADS * 32) / 256, 256>>>((float*)pK, KVHEADS * HDIM, KVHEADS);

    // split Q/K/V into bf16 hi/lo planes for the mma flash kernel
    split_kernel<<<(MROWS * 2048 / 4) / 256, 256>>>((const float*)pQ, (__nv_bfloat16*)pQh, (__nv_bfloat16*)pQl, MROWS * 2048 / 4);
    split_kernel<<<(MROWS * 512  / 4) / 256, 256>>>((const float*)pK, (__nv_bfloat16*)pKh, (__nv_bfloat16*)pKl, MROWS * 512 / 4);
    split_kernel<<<(MROWS * 512  / 4) / 256, 256>>>((const float*)pV, (__nv_bfloat16*)pVh, (__nv_bfloat16*)pVl, MROWS * 512 / 4);

    // Flash attention (tensor cores, split-bf16)
    cudaFuncSetAttribute(flash_mma_kernel, cudaFuncAttributeMaxDynamicSharedMemorySize, FL_SMEM);
    flash_mma_kernel<<<dim3(SEQ / 64, NHEADS, BATCH), 128, FL_SMEM>>>(
        (const __nv_bfloat16*)pQh, (const __nv_bfloat16*)pQl,
        (const __nv_bfloat16*)pKh, (const __nv_bfloat16*)pKl,
        (const __nv_bfloat16*)pVh, (const __nv_bfloat16*)pVl,
        mask, (__nv_bfloat16*)pOh, (__nv_bfloat16*)pOl);

    // Output projection (tensor cores)
    gemm_bf16x3<<<dim3(2048 / 128, MROWS / 128), 256, GEMM_SMEM>>>(
        (const __nv_bfloat16*)pOh, (const __nv_bfloat16*)pOl,
        (const __nv_bfloat16*)pWoh, (const __nv_bfloat16*)pWol,
        out, MROWS, 2048, DMODEL);
}

// round 10
// speedup vs baseline: 2.9060x; 1.0016x over previous
#include <cuda_runtime.h>
#include <cuda_bf16.h>
#include <math.h>
#include <stdint.h>

#define BATCH   2
#define SEQ     2048
#define DMODEL  2048
#define NHEADS  32
#define HDIM    64
#define KVHEADS 8
#define MROWS   (BATCH*SEQ)          // 4096

// ---------------- scratch (device globals; no allocation allowed) ----------
__device__ float g_Q[MROWS * NHEADS * HDIM];    // 4096 x 2048
__device__ float g_K[MROWS * KVHEADS * HDIM];   // 4096 x 512
__device__ float g_V[MROWS * KVHEADS * HDIM];   // 4096 x 512
__device__ float g_freqs[32];

// split-bf16 planes
__device__ __nv_bfloat16 g_xh [MROWS * DMODEL];
__device__ __nv_bfloat16 g_xl [MROWS * DMODEL];
__device__ __nv_bfloat16 g_Wqh[DMODEL * 2048];
__device__ __nv_bfloat16 g_Wql[DMODEL * 2048];
__device__ __nv_bfloat16 g_Wkh[DMODEL * 512];
__device__ __nv_bfloat16 g_Wkl[DMODEL * 512];
__device__ __nv_bfloat16 g_Wvh[DMODEL * 512];
__device__ __nv_bfloat16 g_Wvl[DMODEL * 512];
__device__ __nv_bfloat16 g_Woh[2048 * DMODEL];
__device__ __nv_bfloat16 g_Wol[2048 * DMODEL];
__device__ __nv_bfloat16 g_Qh [MROWS * 2048];
__device__ __nv_bfloat16 g_Ql [MROWS * 2048];
__device__ __nv_bfloat16 g_Kh [MROWS * 512];
__device__ __nv_bfloat16 g_Kl [MROWS * 512];
__device__ __nv_bfloat16 g_Vh [MROWS * 512];
__device__ __nv_bfloat16 g_Vl [MROWS * 512];
__device__ __nv_bfloat16 g_Oh [MROWS * 2048];
__device__ __nv_bfloat16 g_Ol [MROWS * 2048];

// ---------------- RoPE frequency table -------------------------------------
__global__ void init_freqs_kernel() {
    int i = threadIdx.x;  // 32 threads
    g_freqs[i] = (float)exp2(-(double)i * (13.287712379549449 / 32.0));
}

// ---------------- fp32 -> (hi, lo) bf16 split -------------------------------
__global__ void __launch_bounds__(256) split_kernel(
    const float* __restrict__ src, __nv_bfloat16* __restrict__ hi,
    __nv_bfloat16* __restrict__ lo, int n4)
{
    const int i = blockIdx.x * blockDim.x + threadIdx.x;
    if (i >= n4) return;
    const float4 f = ((const float4*)src)[i];
    __nv_bfloat16 h[4], l[4];
    const float fv[4] = {f.x, f.y, f.z, f.w};
#pragma unroll
    for (int k = 0; k < 4; k++) {
        h[k] = __float2bfloat16(fv[k]);
        l[k] = __float2bfloat16(fv[k] - __bfloat162float(h[k]));
    }
    *(uint2*)(hi + 4 * (size_t)i) = *(uint2*)h;
    *(uint2*)(lo + 4 * (size_t)i) = *(uint2*)l;
}

// ---------------- PTX helpers ----------------------------------------------
__device__ __forceinline__ void cpasync16(void* s, const void* g) {
    unsigned sa = (unsigned)__cvta_generic_to_shared(s);
    asm volatile("cp.async.cg.shared.global [%0], [%1], 16;\n" :: "r"(sa), "l"(g));
}
__device__ __forceinline__ void cp_commit() {
    asm volatile("cp.async.commit_group;\n" ::: "memory");
}
__device__ __forceinline__ void cp_wait0() {
    asm volatile("cp.async.wait_group 0;\n" ::: "memory");
}
__device__ __forceinline__ void cp_wait1() {
    asm volatile("cp.async.wait_group 1;\n" ::: "memory");
}
__device__ __forceinline__ void ldsm4(unsigned* r, const void* p) {
    unsigned a = (unsigned)__cvta_generic_to_shared(p);
    asm volatile("ldmatrix.sync.aligned.m8n8.x4.shared.b16 {%0,%1,%2,%3}, [%4];"
                 : "=r"(r[0]), "=r"(r[1]), "=r"(r[2]), "=r"(r[3]) : "r"(a));
}
__device__ __forceinline__ void ldsm4t(unsigned* r, const void* p) {
    unsigned a = (unsigned)__cvta_generic_to_shared(p);
    asm volatile("ldmatrix.sync.aligned.m8n8.x4.trans.shared.b16 {%0,%1,%2,%3}, [%4];"
                 : "=r"(r[0]), "=r"(r[1]), "=r"(r[2]), "=r"(r[3]) : "r"(a));
}
__device__ __forceinline__ void mma16816(float* d, const unsigned* a, const unsigned* b) {
    asm volatile("mma.sync.aligned.m16n8k16.row.col.f32.bf16.bf16.f32 "
                 "{%0,%1,%2,%3},{%4,%5,%6,%7},{%8,%9},{%0,%1,%2,%3};"
                 : "+f"(d[0]), "+f"(d[1]), "+f"(d[2]), "+f"(d[3])
                 : "r"(a[0]), "r"(a[1]), "r"(a[2]), "r"(a[3]), "r"(b[0]), "r"(b[1]));
}
__device__ __forceinline__ unsigned swz(unsigned o) { return o ^ ((o >> 3) & 0x70); }

__device__ __forceinline__ void f2bf_split(float x, float y, unsigned& hi, unsigned& lo) {
    __nv_bfloat162 h = __floats2bfloat162_rn(x, y);
    float rx = x - __bfloat162float(h.x);
    float ry = y - __bfloat162float(h.y);
    __nv_bfloat162 l = __floats2bfloat162_rn(rx, ry);
    hi = *(unsigned*)&h; lo = *(unsigned*)&l;
}

// ---------------- split-bf16 3-product tensor-core GEMM ---------------------
// C(MxN) = Ah*Bh + Ah*Bl + Al*Bh, fp32 accum.  A row-major [M,K], B [K,N].
// BM=128 BN=128 BK=32, 256 threads = 8 warps (2 x 4), warp tile 64x32.
// 3-stage cp.async pipeline, ONE __syncthreads per K-iteration.
#define SA_STRIDE 56   // bf16; 112B row: 16B-aligned, distinct banks for LDSM
#define SB_STRIDE 136  // 272B row
#define SA_PLANE  (128 * SA_STRIDE)   // 7168 elems
#define SB_PLANE  (32 * SB_STRIDE)    // 4352 elems
#define STAGE_ELEMS (2 * SA_PLANE + 2 * SB_PLANE)   // 23040 elems = 46080 B
#define GEMM_SMEM (3 * STAGE_ELEMS * 2)             // 138240 B (3 stages)

__global__ void __launch_bounds__(256, 1) gemm_bf16x3(
    const __nv_bfloat16* __restrict__ Ah, const __nv_bfloat16* __restrict__ Al,
    const __nv_bfloat16* __restrict__ Bh, const __nv_bfloat16* __restrict__ Bl,
    float* __restrict__ C, int M, int N, int K)
{
    extern __shared__ __nv_bfloat16 sm[];
    const int tid  = threadIdx.x;
    const int warp = tid >> 5, lane = tid & 31;
    const int bm = blockIdx.y * 128, bn = blockIdx.x * 128;
    const int wm = (warp >> 2) * 64, wn = (warp & 3) * 32;

    float acc[4][4][4];
#pragma unroll
    for (int i = 0; i < 4; i++)
#pragma unroll
        for (int j = 0; j < 4; j++)
#pragma unroll
            for (int d = 0; d < 4; d++) acc[i][j][d] = 0.0f;

    const int kIters = K >> 5;

#define LOAD_STAGE(s, k0) do {                                                  \
        __nv_bfloat16* Sah = sm + (s) * STAGE_ELEMS;                            \
        __nv_bfloat16* Sal = Sah + SA_PLANE;                                    \
        __nv_bfloat16* Sbh = Sal + SA_PLANE;                                    \
        __nv_bfloat16* Sbl = Sbh + SB_PLANE;                                    \
        _Pragma("unroll")                                                       \
        for (int cc = 0; cc < 2; cc++) {                                        \
            const int c  = tid + cc * 256;                                      \
            const int ar = c >> 2, ac = c & 3;                                  \
            const size_t ga = (size_t)(bm + ar) * K + (k0) + ac * 8;            \
            cpasync16(Sah + ar * SA_STRIDE + ac * 8, Ah + ga);                  \
            cpasync16(Sal + ar * SA_STRIDE + ac * 8, Al + ga);                  \
            const int br = c >> 4, bc = c & 15;                                 \
            const size_t gb = (size_t)((k0) + br) * N + bn + bc * 8;            \
            cpasync16(Sbh + br * SB_STRIDE + bc * 8, Bh + gb);                  \
            cpasync16(Sbl + br * SB_STRIDE + bc * 8, Bl + gb);                  \
        }                                                                       \
        cp_commit();                                                            \
    } while (0)

    LOAD_STAGE(0, 0);
    LOAD_STAGE(1, 32);

    for (int it = 0; it < kIters; it++) {
        const int s = it % 3;
        if (it + 1 < kIters) cp_wait1(); else cp_wait0();
        __syncthreads();
        if (it + 2 < kIters) LOAD_STAGE((it + 2) % 3, (it + 2) * 32);

        const __nv_bfloat16* Sah = sm + s * STAGE_ELEMS;
        const __nv_bfloat16* Sal = Sah + SA_PLANE;
        const __nv_bfloat16* Sbh = Sal + SA_PLANE;
        const __nv_bfloat16* Sbl = Sbh + SB_PLANE;

#pragma unroll
        for (int kk = 0; kk < 2; kk++) {
            unsigned ah[4][4], al[4][4];
#pragma unroll
            for (int i = 0; i < 4; i++) {
                const int off = (wm + i * 16 + (lane & 15)) * SA_STRIDE
                              + kk * 16 + (lane >> 4) * 8;
                ldsm4(ah[i], Sah + off);
                ldsm4(al[i], Sal + off);
            }
            unsigned bh[4][2], bl[4][2];
#pragma unroll
            for (int jj = 0; jj < 2; jj++) {
                const int off = (kk * 16 + (lane & 15)) * SB_STRIDE
                              + wn + jj * 16 + (lane >> 4) * 8;
                unsigned t[4];
                ldsm4t(t, Sbh + off);
                bh[2 * jj][0] = t[0]; bh[2 * jj][1] = t[1];
                bh[2 * jj + 1][0] = t[2]; bh[2 * jj + 1][1] = t[3];
                ldsm4t(t, Sbl + off);
                bl[2 * jj][0] = t[0]; bl[2 * jj][1] = t[1];
                bl[2 * jj + 1][0] = t[2]; bl[2 * jj + 1][1] = t[3];
            }
#pragma unroll
            for (int i = 0; i < 4; i++)
#pragma unroll
                for (int j = 0; j < 4; j++) {
                    mma16816(acc[i][j], ah[i], bh[j]);
                    mma16816(acc[i][j], ah[i], bl[j]);
                    mma16816(acc[i][j], al[i], bh[j]);
                }
        }
    }

    // epilogue
#pragma unroll
    for (int i = 0; i < 4; i++)
#pragma unroll
        for (int j = 0; j < 4; j++) {
            const int r = bm + wm + i * 16 + (lane >> 2);
            const int c = bn + wn + j * 8 + (lane & 3) * 2;
            *(float2*)(C + (size_t)r * N + c)       = make_float2(acc[i][j][0], acc[i][j][1]);
            *(float2*)(C + (size_t)(r + 8) * N + c) = make_float2(acc[i][j][2], acc[i][j][3]);
        }
}

// ---------------- fused RoPE + bf16 hi/lo split -----------------------------
// Reads fp32 QKV-projection output, applies rotary embedding, writes split
// bf16 planes directly (no fp32 writeback, no separate split pass).
__global__ void rope_split_kernel(
    const float* __restrict__ buf, __nv_bfloat16* __restrict__ hi,
    __nv_bfloat16* __restrict__ lo, int rowlen, int heads)
{
    const int idx = blockIdx.x * blockDim.x + threadIdx.x;
    const int total = MROWS * heads * 32;
    if (idx >= total) return;
    const int j  = idx & 31;
    const int t1 = idx >> 5;
    const int h  = t1 % heads;
    const int r  = t1 / heads;
    const float tn = (float)(r & (SEQ - 1));

    const size_t base = (size_t)r * rowlen + h * HDIM;
    const float x1 = buf[base + j];
    const float x2 = buf[base + j + 32];

    const float a1 = tn * g_freqs[j >> 1];
    const float a2 = tn * g_freqs[16 + (j >> 1)];
    float s1, c1, s2, c2;
    sincosf(a1, &s1, &c1);
    sincosf(a2, &s2, &c2);
    const float o1 = x1 * c1 - x2 * s1;
    const float o2 = x1 * s2 + x2 * c2;

    const __nv_bfloat16 h1 = __float2bfloat16(o1);
    const __nv_bfloat16 l1 = __float2bfloat16(o1 - __bfloat162float(h1));
    const __nv_bfloat16 h2 = __float2bfloat16(o2);
    const __nv_bfloat16 l2 = __float2bfloat16(o2 - __bfloat162float(h2));
    hi[base + j]      = h1;  lo[base + j]      = l1;
    hi[base + j + 32] = h2;  lo[base + j + 32] = l2;
}

// ---------------- Flash attention on tensor cores (split-bf16) -------------
#define FL_SMEM (6 * 8192 + 256)

__global__ void __launch_bounds__(128, 2) flash_mma_kernel(
    const __nv_bfloat16* __restrict__ Qh, const __nv_bfloat16* __restrict__ Ql,
    const __nv_bfloat16* __restrict__ Kh, const __nv_bfloat16* __restrict__ Kl,
    const __nv_bfloat16* __restrict__ Vh, const __nv_bfloat16* __restrict__ Vl,
    const int* __restrict__ mask,
    __nv_bfloat16* __restrict__ Oh, __nv_bfloat16* __restrict__ Ol)
{
    extern __shared__ char smc[];
    char* Qsh = smc;
    char* Qsl = smc + 8192;
    char* Ksh = smc + 16384;
    char* Ksl = smc + 24576;
    char* Vsh = smc + 32768;
    char* Vsl = smc + 40960;
    float* bias = (float*)(smc + 49152);

    const int qt = (gridDim.x - 1) - blockIdx.x;
    const int h = blockIdx.y, b = blockIdx.z;
    const int kvh = h >> 2;
    const int tid = threadIdx.x, warp = tid >> 5, lane = tid & 31;
    const int g = lane >> 2, t2 = (lane & 3) * 2;
    const float scale = 0.125f;
    const float slope = exp2f(-0.25f * (float)(h + 1));

    {
        const size_t base = (size_t)(b * SEQ + qt * 64) * 2048 + h * 64;
#pragma unroll
        for (int cc = 0; cc < 4; cc++) {
            const int c = tid + cc * 128;
            const int row = c >> 3, k8 = c & 7;
            const size_t gp = base + (size_t)row * 2048 + k8 * 8;
            const unsigned so = swz(row * 128 + k8 * 16);
            cpasync16(Qsh + so, Qh + gp);
            cpasync16(Qsl + so, Ql + gp);
        }
        cp_commit(); cp_wait0();
        __syncthreads();
    }
    unsigned qh[4][4], ql[4][4];
#pragma unroll
    for (int kc = 0; kc < 4; kc++) {
        const unsigned ad = swz((warp * 16 + (lane & 15)) * 128 + kc * 32 + (lane >> 4) * 16);
        ldsm4(qh[kc], Qsh + ad);
        ldsm4(ql[kc], Qsl + ad);
    }

    float o[8][4];
#pragma unroll
    for (int j = 0; j < 8; j++)
#pragma unroll
        for (int d = 0; d < 4; d++) o[j][d] = 0.0f;
    float m0 = -1e30f, m1 = -1e30f, l0 = 0.0f, l1 = 0.0f;
    const int qrow0 = qt * 64 + warp * 16 + g;

    for (int kt = 0; kt <= qt; kt++) {
        __syncthreads();
        {
            const size_t kbase = (size_t)(b * SEQ + kt * 64) * 512 + kvh * 64;
#pragma unroll
            for (int cc = 0; cc < 4; cc++) {
                const int c = tid + cc * 128;
                const int row = c >> 3, k8 = c & 7;
                const size_t gp = kbase + (size_t)row * 512 + k8 * 8;
                const unsigned so = swz(row * 128 + k8 * 16);
                cpasync16(Ksh + so, Kh + gp);
                cpasync16(Ksl + so, Kl + gp);
                cpasync16(Vsh + so, Vh + gp);
                cpasync16(Vsl + so, Vl + gp);
            }
        }
        if (tid < 64) bias[tid] = mask[b * SEQ + kt * 64 + tid] ? 0.0f : -1e30f;
        cp_commit(); cp_wait0();
        __syncthreads();

        float s[8][4];
#pragma unroll
        for (int j = 0; j < 8; j++)
#pragma unroll
            for (int d = 0; d < 4; d++) s[j][d] = 0.0f;

#pragma unroll
        for (int kc = 0; kc < 4; kc++)
#pragma unroll
            for (int jj = 0; jj < 4; jj++) {
                const unsigned ad = swz((jj * 16 + (lane & 15)) * 128 + kc * 32 + (lane >> 4) * 16);
                unsigned tt[4], uu[4];
                ldsm4(tt, Ksh + ad);
                ldsm4(uu, Ksl + ad);
                unsigned bh[2], bl[2];
                bh[0] = tt[0]; bh[1] = tt[2]; bl[0] = uu[0]; bl[1] = uu[2];
                mma16816(s[2 * jj], qh[kc], bh);
                mma16816(s[2 * jj], ql[kc], bh);
                mma16816(s[2 * jj], qh[kc], bl);
                bh[0] = tt[1]; bh[1] = tt[3]; bl[0] = uu[1]; bl[1] = uu[3];
                mma16816(s[2 * jj + 1], qh[kc], bh);
                mma16816(s[2 * jj + 1], ql[kc], bh);
                mma16816(s[2 * jj + 1], qh[kc], bl);
            }

#pragma unroll
        for (int j = 0; j < 8; j++) {
            const int kg = kt * 64 + j * 8 + t2;
            const float b0 = bias[j * 8 + t2];
            const float b1 = bias[j * 8 + t2 + 1];
            const float al0 = fmaf(slope, (float)kg, b0);
            const float al1 = fmaf(slope, (float)(kg + 1), b1);
            float v0 = fmaf(s[j][0], scale, al0);
            float v1 = fmaf(s[j][1], scale, al1);
            float v2 = fmaf(s[j][2], scale, al0);
            float v3 = fmaf(s[j][3], scale, al1);
            if (kg     > qrow0)     v0 = -1e30f;
            if (kg + 1 > qrow0)     v1 = -1e30f;
            if (kg     > qrow0 + 8) v2 = -1e30f;
            if (kg + 1 > qrow0 + 8) v3 = -1e30f;
            s[j][0] = v0; s[j][1] = v1; s[j][2] = v2; s[j][3] = v3;
        }

        float mx0 = -1e30f, mx1 = -1e30f;
#pragma unroll
        for (int j = 0; j < 8; j++) {
            mx0 = fmaxf(mx0, fmaxf(s[j][0], s[j][1]));
            mx1 = fmaxf(mx1, fmaxf(s[j][2], s[j][3]));
        }
        mx0 = fmaxf(mx0, __shfl_xor_sync(0xffffffffu, mx0, 1));
        mx0 = fmaxf(mx0, __shfl_xor_sync(0xffffffffu, mx0, 2));
        mx1 = fmaxf(mx1, __shfl_xor_sync(0xffffffffu, mx1, 1));
        mx1 = fmaxf(mx1, __shfl_xor_sync(0xffffffffu, mx1, 2));
        const float mn0 = fmaxf(m0, mx0), mn1 = fmaxf(m1, mx1);
        const float cr0 = __expf(m0 - mn0), cr1 = __expf(m1 - mn1);
        float ps0 = 0.0f, ps1 = 0.0f;
#pragma unroll
        for (int j = 0; j < 8; j++) {
            s[j][0] = __expf(s[j][0] - mn0);
            s[j][1] = __expf(s[j][1] - mn0);
            s[j][2] = __expf(s[j][2] - mn1);
            s[j][3] = __expf(s[j][3] - mn1);
            ps0 += s[j][0] + s[j][1];
            ps1 += s[j][2] + s[j][3];
        }
        ps0 += __shfl_xor_sync(0xffffffffu, ps0, 1);
        ps0 += __shfl_xor_sync(0xffffffffu, ps0, 2);
        ps1 += __shfl_xor_sync(0xffffffffu, ps1, 1);
        ps1 += __shfl_xor_sync(0xffffffffu, ps1, 2);
        l0 = l0 * cr0 + ps0; m0 = mn0;
        l1 = l1 * cr1 + ps1; m1 = mn1;
#pragma unroll
        for (int j = 0; j < 8; j++) {
            o[j][0] *= cr0; o[j][1] *= cr0;
            o[j][2] *= cr1; o[j][3] *= cr1;
        }

#pragma unroll
        for (int kc = 0; kc < 4; kc++) {
            unsigned ph[4], pl[4];
            f2bf_split(s[2 * kc][0],     s[2 * kc][1],     ph[0], pl[0]);
            f2bf_split(s[2 * kc][2],     s[2 * kc][3],     ph[1], pl[1]);
            f2bf_split(s[2 * kc + 1][0], s[2 * kc + 1][1], ph[2], pl[2]);
            f2bf_split(s[2 * kc + 1][2], s[2 * kc + 1][3], ph[3], pl[3]);
#pragma unroll
            for (int jj = 0; jj < 4; jj++) {
                const unsigned ad = swz((kc * 16 + (lane & 15)) * 128 + jj * 32 + (lane >> 4) * 16);
                unsigned tt[4], uu[4];
                ldsm4t(tt, Vsh + ad);
                ldsm4t(uu, Vsl + ad);
                unsigned bh[2], bl[2];
                bh[0] = tt[0]; bh[1] = tt[1]; bl[0] = uu[0]; bl[1] = uu[1];
                mma16816(o[2 * jj], ph, bh);
                mma16816(o[2 * jj], pl, bh);
                mma16816(o[2 * jj], ph, bl);
                bh[0] = tt[2]; bh[1] = tt[3]; bl[0] = uu[2]; bl[1] = uu[3];
                mma16816(o[2 * jj + 1], ph, bh);
                mma16816(o[2 * jj + 1], pl, bh);
                mma16816(o[2 * jj + 1], ph, bl);
            }
        }
    }

    const float inv0 = 1.0f / l0, inv1 = 1.0f / l1;
#pragma unroll
    for (int j = 0; j < 8; j++) {
        const size_t p0 = (size_t)(b * SEQ + qrow0) * 2048 + h * 64 + j * 8 + t2;
        unsigned hh, ll;
        f2bf_split(o[j][0] * inv0, o[j][1] * inv0, hh, ll);
        *(unsigned*)(Oh + p0) = hh;
        *(unsigned*)(Ol + p0) = ll;
        f2bf_split(o[j][2] * inv1, o[j][3] * inv1, hh, ll);
        *(unsigned*)(Oh + p0 + 8 * 2048) = hh;
        *(unsigned*)(Ol + p0 + 8 * 2048) = ll;
    }
}

// ---------------- host launcher -------------------------------------------
extern "C" void kernel_launch(void* const* d_in, const int* in_sizes, int n_in,
                              void* d_out, int out_size)
{
    const float* x    = (const float*)d_in[0];
    const int*   mask = (const int*)  d_in[1];
    const float* Wq   = (const float*)d_in[2];
    const float* Wk   = (const float*)d_in[3];
    const float* Wv   = (const float*)d_in[4];
    const float* Wo   = (const float*)d_in[5];
    float* out = (float*)d_out;

    void *pQ, *pK, *pV;
    void *pxh, *pxl, *pWqh, *pWql, *pWkh, *pWkl, *pWvh, *pWvl, *pWoh, *pWol;
    void *pQh, *pQl, *pKh, *pKl, *pVh, *pVl, *pOh, *pOl;
    cudaGetSymbolAddress(&pQ, g_Q);  cudaGetSymbolAddress(&pK, g_K);
    cudaGetSymbolAddress(&pV, g_V);
    cudaGetSymbolAddress(&pxh, g_xh);  cudaGetSymbolAddress(&pxl, g_xl);
    cudaGetSymbolAddress(&pWqh, g_Wqh); cudaGetSymbolAddress(&pWql, g_Wql);
    cudaGetSymbolAddress(&pWkh, g_Wkh); cudaGetSymbolAddress(&pWkl, g_Wkl);
    cudaGetSymbolAddress(&pWvh, g_Wvh); cudaGetSymbolAddress(&pWvl, g_Wvl);
    cudaGetSymbolAddress(&pWoh, g_Woh); cudaGetSymbolAddress(&pWol, g_Wol);
    cudaGetSymbolAddress(&pQh, g_Qh);   cudaGetSymbolAddress(&pQl, g_Ql);
    cudaGetSymbolAddress(&pKh, g_Kh);   cudaGetSymbolAddress(&pKl, g_Kl);
    cudaGetSymbolAddress(&pVh, g_Vh);   cudaGetSymbolAddress(&pVl, g_Vl);
    cudaGetSymbolAddress(&pOh, g_Oh);   cudaGetSymbolAddress(&pOl, g_Ol);

    init_freqs_kernel<<<1, 32>>>();

    // split fp32 operands into (hi, lo) bf16 planes
    split_kernel<<<(MROWS * DMODEL / 4) / 256, 256>>>(x,  (__nv_bfloat16*)pxh, (__nv_bfloat16*)pxl, MROWS * DMODEL / 4);
    split_kernel<<<(DMODEL * 2048 / 4) / 256, 256>>>(Wq, (__nv_bfloat16*)pWqh, (__nv_bfloat16*)pWql, DMODEL * 2048 / 4);
    split_kernel<<<(DMODEL * 512  / 4) / 256, 256>>>(Wk, (__nv_bfloat16*)pWkh, (__nv_bfloat16*)pWkl, DMODEL * 512 / 4);
    split_kernel<<<(DMODEL * 512  / 4) / 256, 256>>>(Wv, (__nv_bfloat16*)pWvh, (__nv_bfloat16*)pWvl, DMODEL * 512 / 4);
    split_kernel<<<(2048 * DMODEL / 4) / 256, 256>>>(Wo, (__nv_bfloat16*)pWoh, (__nv_bfloat16*)pWol, 2048 * DMODEL / 4);

    cudaFuncSetAttribute(gemm_bf16x3, cudaFuncAttributeMaxDynamicSharedMemorySize, GEMM_SMEM);

    // QKV projections (tensor cores)
    gemm_bf16x3<<<dim3(2048 / 128, MROWS / 128), 256, GEMM_SMEM>>>(
        (const __nv_bfloat16*)pxh, (const __nv_bfloat16*)pxl,
        (const __nv_bfloat16*)pWqh, (const __nv_bfloat16*)pWql,
        (float*)pQ, MROWS, 2048, DMODEL);
    gemm_bf16x3<<<dim3(512 / 128, MROWS / 128), 256, GEMM_SMEM>>>(
        (const __nv_bfloat16*)pxh, (const __nv_bfloat16*)pxl,
        (const __nv_bfloat16*)pWkh, (const __nv_bfloat16*)pWkl,
        (float*)pK, MROWS, 512, DMODEL);
    gemm_bf16x3<<<dim3(512 / 128, MROWS / 128), 256, GEMM_SMEM>>>(
        (const __nv_bfloat16*)pxh, (const __nv_bfloat16*)pxl,
        (const __nv_bfloat16*)pWvh, (const __nv_bfloat16*)pWvl,
        (float*)pV, MROWS, 512, DMODEL);

    // fused RoPE + split for Q and K; plain split for V
    rope_split_kernel<<<(MROWS * NHEADS  * 32) / 256, 256>>>(
        (const float*)pQ, (__nv_bfloat16*)pQh, (__nv_bfloat16*)pQl, NHEADS * HDIM, NHEADS);
    rope_split_kernel<<<(MROWS * KVHEADS * 32) / 256, 256>>>(
        (const float*)pK, (__nv_bfloat16*)pKh, (__nv_bfloat16*)pKl, KVHEADS * HDIM, KVHEADS);
    split_kernel<<<(MROWS * 512 / 4) / 256, 256>>>(
        (const float*)pV, (__nv_bfloat16*)pVh, (__nv_bfloat16*)pVl, MROWS * 512 / 4);

    // Flash attention (tensor cores, split-bf16)
    cudaFuncSetAttribute(flash_mma_kernel, cudaFuncAttributeMaxDynamicSharedMemorySize, FL_SMEM);
    flash_mma_kernel<<<dim3(SEQ / 64, NHEADS, BATCH), 128, FL_SMEM>>>(
        (const __nv_bfloat16*)pQh, (const __nv_bfloat16*)pQl,
        (const __nv_bfloat16*)pKh, (const __nv_bfloat16*)pKl,
        (const __nv_bfloat16*)pVh, (const __nv_bfloat16*)pVl,
        mask, (__nv_bfloat16*)pOh, (__nv_bfloat16*)pOl);

    // Output projection (tensor cores)
    gemm_bf16x3<<<dim3(2048 / 128, MROWS / 128), 256, GEMM_SMEM>>>(
        (const __nv_bfloat16*)pOh, (const __nv_bfloat16*)pOl,
        (const __nv_bfloat16*)pWoh, (const __nv_bfloat16*)pWol,
        out, MROWS, 2048, DMODEL);
}

// round 11
// speedup vs baseline: 2.9071x; 1.0004x over previous
#include <cuda_runtime.h>
#include <cuda_bf16.h>
#include <math.h>
#include <stdint.h>

#define BATCH   2
#define SEQ     2048
#define DMODEL  2048
#define NHEADS  32
#define HDIM    64
#define KVHEADS 8
#define MROWS   (BATCH*SEQ)          // 4096

// ---------------- scratch (device globals; no allocation allowed) ----------
__device__ float g_Q[MROWS * NHEADS * HDIM];    // 4096 x 2048
__device__ float g_K[MROWS * KVHEADS * HDIM];   // 4096 x 512
__device__ float g_V[MROWS * KVHEADS * HDIM];   // 4096 x 512
__device__ float g_freqs[32];

// split-bf16 planes
__device__ __nv_bfloat16 g_xh [MROWS * DMODEL];
__device__ __nv_bfloat16 g_xl [MROWS * DMODEL];
__device__ __nv_bfloat16 g_Wqh[DMODEL * 2048];
__device__ __nv_bfloat16 g_Wql[DMODEL * 2048];
__device__ __nv_bfloat16 g_Wkh[DMODEL * 512];
__device__ __nv_bfloat16 g_Wkl[DMODEL * 512];
__device__ __nv_bfloat16 g_Wvh[DMODEL * 512];
__device__ __nv_bfloat16 g_Wvl[DMODEL * 512];
__device__ __nv_bfloat16 g_Woh[2048 * DMODEL];
__device__ __nv_bfloat16 g_Wol[2048 * DMODEL];
__device__ __nv_bfloat16 g_Qh [MROWS * 2048];
__device__ __nv_bfloat16 g_Ql [MROWS * 2048];
__device__ __nv_bfloat16 g_Kh [MROWS * 512];
__device__ __nv_bfloat16 g_Kl [MROWS * 512];
__device__ __nv_bfloat16 g_Vh [MROWS * 512];
__device__ __nv_bfloat16 g_Vl [MROWS * 512];
__device__ __nv_bfloat16 g_Oh [MROWS * 2048];
__device__ __nv_bfloat16 g_Ol [MROWS * 2048];

// ---------------- RoPE frequency table -------------------------------------
__global__ void init_freqs_kernel() {
    int i = threadIdx.x;  // 32 threads
    g_freqs[i] = (float)exp2(-(double)i * (13.287712379549449 / 32.0));
}

// ---------------- fp32 -> (hi, lo) bf16 split -------------------------------
__global__ void __launch_bounds__(256) split_kernel(
    const float* __restrict__ src, __nv_bfloat16* __restrict__ hi,
    __nv_bfloat16* __restrict__ lo, int n4)
{
    const int i = blockIdx.x * blockDim.x + threadIdx.x;
    if (i >= n4) return;
    const float4 f = ((const float4*)src)[i];
    __nv_bfloat16 h[4], l[4];
    const float fv[4] = {f.x, f.y, f.z, f.w};
#pragma unroll
    for (int k = 0; k < 4; k++) {
        h[k] = __float2bfloat16(fv[k]);
        l[k] = __float2bfloat16(fv[k] - __bfloat162float(h[k]));
    }
    *(uint2*)(hi + 4 * (size_t)i) = *(uint2*)h;
    *(uint2*)(lo + 4 * (size_t)i) = *(uint2*)l;
}

// ---------------- PTX helpers ----------------------------------------------
__device__ __forceinline__ void cpasync16(void* s, const void* g) {
    unsigned sa = (unsigned)__cvta_generic_to_shared(s);
    asm volatile("cp.async.cg.shared.global [%0], [%1], 16;\n" :: "r"(sa), "l"(g));
}
__device__ __forceinline__ void cp_commit() {
    asm volatile("cp.async.commit_group;\n" ::: "memory");
}
__device__ __forceinline__ void cp_wait0() {
    asm volatile("cp.async.wait_group 0;\n" ::: "memory");
}
__device__ __forceinline__ void cp_wait1() {
    asm volatile("cp.async.wait_group 1;\n" ::: "memory");
}
__device__ __forceinline__ void ldsm4(unsigned* r, const void* p) {
    unsigned a = (unsigned)__cvta_generic_to_shared(p);
    asm volatile("ldmatrix.sync.aligned.m8n8.x4.shared.b16 {%0,%1,%2,%3}, [%4];"
                 : "=r"(r[0]), "=r"(r[1]), "=r"(r[2]), "=r"(r[3]) : "r"(a));
}
__device__ __forceinline__ void ldsm4t(unsigned* r, const void* p) {
    unsigned a = (unsigned)__cvta_generic_to_shared(p);
    asm volatile("ldmatrix.sync.aligned.m8n8.x4.trans.shared.b16 {%0,%1,%2,%3}, [%4];"
                 : "=r"(r[0]), "=r"(r[1]), "=r"(r[2]), "=r"(r[3]) : "r"(a));
}
__device__ __forceinline__ void mma16816(float* d, const unsigned* a, const unsigned* b) {
    asm volatile("mma.sync.aligned.m16n8k16.row.col.f32.bf16.bf16.f32 "
                 "{%0,%1,%2,%3},{%4,%5,%6,%7},{%8,%9},{%0,%1,%2,%3};"
                 : "+f"(d[0]), "+f"(d[1]), "+f"(d[2]), "+f"(d[3])
                 : "r"(a[0]), "r"(a[1]), "r"(a[2]), "r"(a[3]), "r"(b[0]), "r"(b[1]));
}
__device__ __forceinline__ unsigned swz(unsigned o) { return o ^ ((o >> 3) & 0x70); }

__device__ __forceinline__ void f2bf_split(float x, float y, unsigned& hi, unsigned& lo) {
    __nv_bfloat162 h = __floats2bfloat162_rn(x, y);
    float rx = x - __bfloat162float(h.x);
    float ry = y - __bfloat162float(h.y);
    __nv_bfloat162 l = __floats2bfloat162_rn(rx, ry);
    hi = *(unsigned*)&h; lo = *(unsigned*)&l;
}

// ---------------- split-bf16 3-product tensor-core GEMM ---------------------
// C(MxN) = Ah*Bh + Ah*Bl + Al*Bh, fp32 accum.  A row-major [M,K], B [K,N].
// BM=128 BN=128 BK=32, 256 threads = 8 warps (2 x 4), warp tile 64x32.
// 3-stage cp.async pipeline; products issued in 3 separated passes so
// dependent HMMAs to the same accumulator are 16 instructions apart.
#define SA_STRIDE 56   // bf16; 112B row: 16B-aligned, distinct banks for LDSM
#define SB_STRIDE 136  // 272B row
#define SA_PLANE  (128 * SA_STRIDE)   // 7168 elems
#define SB_PLANE  (32 * SB_STRIDE)    // 4352 elems
#define STAGE_ELEMS (2 * SA_PLANE + 2 * SB_PLANE)   // 23040 elems = 46080 B
#define GEMM_SMEM (3 * STAGE_ELEMS * 2)             // 138240 B (3 stages)

__global__ void __launch_bounds__(256, 1) gemm_bf16x3(
    const __nv_bfloat16* __restrict__ Ah, const __nv_bfloat16* __restrict__ Al,
    const __nv_bfloat16* __restrict__ Bh, const __nv_bfloat16* __restrict__ Bl,
    float* __restrict__ C, int M, int N, int K)
{
    extern __shared__ __nv_bfloat16 sm[];
    const int tid  = threadIdx.x;
    const int warp = tid >> 5, lane = tid & 31;
    const int bm = blockIdx.y * 128, bn = blockIdx.x * 128;
    const int wm = (warp >> 2) * 64, wn = (warp & 3) * 32;

    float acc[4][4][4];
#pragma unroll
    for (int i = 0; i < 4; i++)
#pragma unroll
        for (int j = 0; j < 4; j++)
#pragma unroll
            for (int d = 0; d < 4; d++) acc[i][j][d] = 0.0f;

    const int kIters = K >> 5;

#define LOAD_STAGE(s, k0) do {                                                  \
        __nv_bfloat16* Sah = sm + (s) * STAGE_ELEMS;                            \
        __nv_bfloat16* Sal = Sah + SA_PLANE;                                    \
        __nv_bfloat16* Sbh = Sal + SA_PLANE;                                    \
        __nv_bfloat16* Sbl = Sbh + SB_PLANE;                                    \
        _Pragma("unroll")                                                       \
        for (int cc = 0; cc < 2; cc++) {                                        \
            const int c  = tid + cc * 256;                                      \
            const int ar = c >> 2, ac = c & 3;                                  \
            const size_t ga = (size_t)(bm + ar) * K + (k0) + ac * 8;            \
            cpasync16(Sah + ar * SA_STRIDE + ac * 8, Ah + ga);                  \
            cpasync16(Sal + ar * SA_STRIDE + ac * 8, Al + ga);                  \
            const int br = c >> 4, bc = c & 15;                                 \
            const size_t gb = (size_t)((k0) + br) * N + bn + bc * 8;            \
            cpasync16(Sbh + br * SB_STRIDE + bc * 8, Bh + gb);                  \
            cpasync16(Sbl + br * SB_STRIDE + bc * 8, Bl + gb);                  \
        }                                                                       \
        cp_commit();                                                            \
    } while (0)

    LOAD_STAGE(0, 0);
    LOAD_STAGE(1, 32);

    for (int it = 0; it < kIters; it++) {
        const int s = it % 3;
        if (it + 1 < kIters) cp_wait1(); else cp_wait0();
        __syncthreads();
        if (it + 2 < kIters) LOAD_STAGE((it + 2) % 3, (it + 2) * 32);

        const __nv_bfloat16* Sah = sm + s * STAGE_ELEMS;
        const __nv_bfloat16* Sal = Sah + SA_PLANE;
        const __nv_bfloat16* Sbh = Sal + SA_PLANE;
        const __nv_bfloat16* Sbl = Sbh + SB_PLANE;

#pragma unroll
        for (int kk = 0; kk < 2; kk++) {
            unsigned ah[4][4], al[4][4];
#pragma unroll
            for (int i = 0; i < 4; i++) {
                const int off = (wm + i * 16 + (lane & 15)) * SA_STRIDE
                              + kk * 16 + (lane >> 4) * 8;
                ldsm4(ah[i], Sah + off);
                ldsm4(al[i], Sal + off);
            }
            unsigned bh[4][2], bl[4][2];
#pragma unroll
            for (int jj = 0; jj < 2; jj++) {
                const int off = (kk * 16 + (lane & 15)) * SB_STRIDE
                              + wn + jj * 16 + (lane >> 4) * 8;
                unsigned t[4];
                ldsm4t(t, Sbh + off);
                bh[2 * jj][0] = t[0]; bh[2 * jj][1] = t[1];
                bh[2 * jj + 1][0] = t[2]; bh[2 * jj + 1][1] = t[3];
                ldsm4t(t, Sbl + off);
                bl[2 * jj][0] = t[0]; bl[2 * jj][1] = t[1];
                bl[2 * jj + 1][0] = t[2]; bl[2 * jj + 1][1] = t[3];
            }
            // three separated product passes: dependent HMMAs 16 apart
#pragma unroll
            for (int i = 0; i < 4; i++)
#pragma unroll
                for (int j = 0; j < 4; j++)
                    mma16816(acc[i][j], ah[i], bh[j]);
#pragma unroll
            for (int i = 0; i < 4; i++)
#pragma unroll
                for (int j = 0; j < 4; j++)
                    mma16816(acc[i][j], ah[i], bl[j]);
#pragma unroll
            for (int i = 0; i < 4; i++)
#pragma unroll
                for (int j = 0; j < 4; j++)
                    mma16816(acc[i][j], al[i], bh[j]);
        }
    }

    // epilogue
#pragma unroll
    for (int i = 0; i < 4; i++)
#pragma unroll
        for (int j = 0; j < 4; j++) {
            const int r = bm + wm + i * 16 + (lane >> 2);
            const int c = bn + wn + j * 8 + (lane & 3) * 2;
            *(float2*)(C + (size_t)r * N + c)       = make_float2(acc[i][j][0], acc[i][j][1]);
            *(float2*)(C + (size_t)(r + 8) * N + c) = make_float2(acc[i][j][2], acc[i][j][3]);
        }
}

// ---------------- fused RoPE + bf16 hi/lo split -----------------------------
__global__ void rope_split_kernel(
    const float* __restrict__ buf, __nv_bfloat16* __restrict__ hi,
    __nv_bfloat16* __restrict__ lo, int rowlen, int heads)
{
    const int idx = blockIdx.x * blockDim.x + threadIdx.x;
    const int total = MROWS * heads * 32;
    if (idx >= total) return;
    const int j  = idx & 31;
    const int t1 = idx >> 5;
    const int h  = t1 % heads;
    const int r  = t1 / heads;
    const float tn = (float)(r & (SEQ - 1));

    const size_t base = (size_t)r * rowlen + h * HDIM;
    const float x1 = buf[base + j];
    const float x2 = buf[base + j + 32];

    const float a1 = tn * g_freqs[j >> 1];
    const float a2 = tn * g_freqs[16 + (j >> 1)];
    float s1, c1, s2, c2;
    sincosf(a1, &s1, &c1);
    sincosf(a2, &s2, &c2);
    const float o1 = x1 * c1 - x2 * s1;
    const float o2 = x1 * s2 + x2 * c2;

    const __nv_bfloat16 h1 = __float2bfloat16(o1);
    const __nv_bfloat16 l1 = __float2bfloat16(o1 - __bfloat162float(h1));
    const __nv_bfloat16 h2 = __float2bfloat16(o2);
    const __nv_bfloat16 l2 = __float2bfloat16(o2 - __bfloat162float(h2));
    hi[base + j]      = h1;  lo[base + j]      = l1;
    hi[base + j + 32] = h2;  lo[base + j + 32] = l2;
}

// ---------------- Flash attention on tensor cores (split-bf16) -------------
#define FL_SMEM (6 * 8192 + 256)

__global__ void __launch_bounds__(128, 2) flash_mma_kernel(
    const __nv_bfloat16* __restrict__ Qh, const __nv_bfloat16* __restrict__ Ql,
    const __nv_bfloat16* __restrict__ Kh, const __nv_bfloat16* __restrict__ Kl,
    const __nv_bfloat16* __restrict__ Vh, const __nv_bfloat16* __restrict__ Vl,
    const int* __restrict__ mask,
    __nv_bfloat16* __restrict__ Oh, __nv_bfloat16* __restrict__ Ol)
{
    extern __shared__ char smc[];
    char* Qsh = smc;
    char* Qsl = smc + 8192;
    char* Ksh = smc + 16384;
    char* Ksl = smc + 24576;
    char* Vsh = smc + 32768;
    char* Vsl = smc + 40960;
    float* bias = (float*)(smc + 49152);

    const int qt = (gridDim.x - 1) - blockIdx.x;
    const int h = blockIdx.y, b = blockIdx.z;
    const int kvh = h >> 2;
    const int tid = threadIdx.x, warp = tid >> 5, lane = tid & 31;
    const int g = lane >> 2, t2 = (lane & 3) * 2;
    const float scale = 0.125f;
    const float slope = exp2f(-0.25f * (float)(h + 1));

    {
        const size_t base = (size_t)(b * SEQ + qt * 64) * 2048 + h * 64;
#pragma unroll
        for (int cc = 0; cc < 4; cc++) {
            const int c = tid + cc * 128;
            const int row = c >> 3, k8 = c & 7;
            const size_t gp = base + (size_t)row * 2048 + k8 * 8;
            const unsigned so = swz(row * 128 + k8 * 16);
            cpasync16(Qsh + so, Qh + gp);
            cpasync16(Qsl + so, Ql + gp);
        }
        cp_commit(); cp_wait0();
        __syncthreads();
    }
    unsigned qh[4][4], ql[4][4];
#pragma unroll
    for (int kc = 0; kc < 4; kc++) {
        const unsigned ad = swz((warp * 16 + (lane & 15)) * 128 + kc * 32 + (lane >> 4) * 16);
        ldsm4(qh[kc], Qsh + ad);
        ldsm4(ql[kc], Qsl + ad);
    }

    float o[8][4];
#pragma unroll
    for (int j = 0; j < 8; j++)
#pragma unroll
        for (int d = 0; d < 4; d++) o[j][d] = 0.0f;
    float m0 = -1e30f, m1 = -1e30f, l0 = 0.0f, l1 = 0.0f;
    const int qrow0 = qt * 64 + warp * 16 + g;

    for (int kt = 0; kt <= qt; kt++) {
        __syncthreads();
        {
            const size_t kbase = (size_t)(b * SEQ + kt * 64) * 512 + kvh * 64;
#pragma unroll
            for (int cc = 0; cc < 4; cc++) {
                const int c = tid + cc * 128;
                const int row = c >> 3, k8 = c & 7;
                const size_t gp = kbase + (size_t)row * 512 + k8 * 8;
                const unsigned so = swz(row * 128 + k8 * 16);
                cpasync16(Ksh + so, Kh + gp);
                cpasync16(Ksl + so, Kl + gp);
                cpasync16(Vsh + so, Vh + gp);
                cpasync16(Vsl + so, Vl + gp);
            }
        }
        if (tid < 64) bias[tid] = mask[b * SEQ + kt * 64 + tid] ? 0.0f : -1e30f;
        cp_commit(); cp_wait0();
        __syncthreads();

        // ---- S = Q K^T: 3 separated product passes per kc ----
        float s[8][4];
#pragma unroll
        for (int j = 0; j < 8; j++)
#pragma unroll
            for (int d = 0; d < 4; d++) s[j][d] = 0.0f;

#pragma unroll
        for (int kc = 0; kc < 4; kc++) {
            unsigned kth[4][4], ktl[4][4];
#pragma unroll
            for (int jj = 0; jj < 4; jj++) {
                const unsigned ad = swz((jj * 16 + (lane & 15)) * 128 + kc * 32 + (lane >> 4) * 16);
                ldsm4(kth[jj], Ksh + ad);
                ldsm4(ktl[jj], Ksl + ad);
            }
            // pass 1: Qh*Kh over all 8 accumulators
#pragma unroll
            for (int jj = 0; jj < 4; jj++) {
                unsigned bfr[2];
                bfr[0] = kth[jj][0]; bfr[1] = kth[jj][2];
                mma16816(s[2 * jj], qh[kc], bfr);
                bfr[0] = kth[jj][1]; bfr[1] = kth[jj][3];
                mma16816(s[2 * jj + 1], qh[kc], bfr);
            }
            // pass 2: Ql*Kh
#pragma unroll
            for (int jj = 0; jj < 4; jj++) {
                unsigned bfr[2];
                bfr[0] = kth[jj][0]; bfr[1] = kth[jj][2];
                mma16816(s[2 * jj], ql[kc], bfr);
                bfr[0] = kth[jj][1]; bfr[1] = kth[jj][3];
                mma16816(s[2 * jj + 1], ql[kc], bfr);
            }
            // pass 3: Qh*Kl
#pragma unroll
            for (int jj = 0; jj < 4; jj++) {
                unsigned bfr[2];
                bfr[0] = ktl[jj][0]; bfr[1] = ktl[jj][2];
                mma16816(s[2 * jj], qh[kc], bfr);
                bfr[0] = ktl[jj][1]; bfr[1] = ktl[jj][3];
                mma16816(s[2 * jj + 1], qh[kc], bfr);
            }
        }

#pragma unroll
        for (int j = 0; j < 8; j++) {
            const int kg = kt * 64 + j * 8 + t2;
            const float b0 = bias[j * 8 + t2];
            const float b1 = bias[j * 8 + t2 + 1];
            const float al0 = fmaf(slope, (float)kg, b0);
            const float al1 = fmaf(slope, (float)(kg + 1), b1);
            float v0 = fmaf(s[j][0], scale, al0);
            float v1 = fmaf(s[j][1], scale, al1);
            float v2 = fmaf(s[j][2], scale, al0);
            float v3 = fmaf(s[j][3], scale, al1);
            if (kg     > qrow0)     v0 = -1e30f;
            if (kg + 1 > qrow0)     v1 = -1e30f;
            if (kg     > qrow0 + 8) v2 = -1e30f;
            if (kg + 1 > qrow0 + 8) v3 = -1e30f;
            s[j][0] = v0; s[j][1] = v1; s[j][2] = v2; s[j][3] = v3;
        }

        float mx0 = -1e30f, mx1 = -1e30f;
#pragma unroll
        for (int j = 0; j < 8; j++) {
            mx0 = fmaxf(mx0, fmaxf(s[j][0], s[j][1]));
            mx1 = fmaxf(mx1, fmaxf(s[j][2], s[j][3]));
        }
        mx0 = fmaxf(mx0, __shfl_xor_sync(0xffffffffu, mx0, 1));
        mx0 = fmaxf(mx0, __shfl_xor_sync(0xffffffffu, mx0, 2));
        mx1 = fmaxf(mx1, __shfl_xor_sync(0xffffffffu, mx1, 1));
        mx1 = fmaxf(mx1, __shfl_xor_sync(0xffffffffu, mx1, 2));
        const float mn0 = fmaxf(m0, mx0), mn1 = fmaxf(m1, mx1);
        const float cr0 = __expf(m0 - mn0), cr1 = __expf(m1 - mn1);
        float ps0 = 0.0f, ps1 = 0.0f;
#pragma unroll
        for (int j = 0; j < 8; j++) {
            s[j][0] = __expf(s[j][0] - mn0);
            s[j][1] = __expf(s[j][1] - mn0);
            s[j][2] = __expf(s[j][2] - mn1);
            s[j][3] = __expf(s[j][3] - mn1);
            ps0 += s[j][0] + s[j][1];
            ps1 += s[j][2] + s[j][3];
        }
        ps0 += __shfl_xor_sync(0xffffffffu, ps0, 1);
        ps0 += __shfl_xor_sync(0xffffffffu, ps0, 2);
        ps1 += __shfl_xor_sync(0xffffffffu, ps1, 1);
        ps1 += __shfl_xor_sync(0xffffffffu, ps1, 2);
        l0 = l0 * cr0 + ps0; m0 = mn0;
        l1 = l1 * cr1 + ps1; m1 = mn1;
#pragma unroll
        for (int j = 0; j < 8; j++) {
            o[j][0] *= cr0; o[j][1] *= cr0;
            o[j][2] *= cr1; o[j][3] *= cr1;
        }

        // ---- O += P V: 3 separated product passes per kc ----
#pragma unroll
        for (int kc = 0; kc < 4; kc++) {
            unsigned ph[4], pl[4];
            f2bf_split(s[2 * kc][0],     s[2 * kc][1],     ph[0], pl[0]);
            f2bf_split(s[2 * kc][2],     s[2 * kc][3],     ph[1], pl[1]);
            f2bf_split(s[2 * kc + 1][0], s[2 * kc + 1][1], ph[2], pl[2]);
            f2bf_split(s[2 * kc + 1][2], s[2 * kc + 1][3], ph[3], pl[3]);
            unsigned vth[4][4], vtl[4][4];
#pragma unroll
            for (int jj = 0; jj < 4; jj++) {
                const unsigned ad = swz((kc * 16 + (lane & 15)) * 128 + jj * 32 + (lane >> 4) * 16);
                ldsm4t(vth[jj], Vsh + ad);
                ldsm4t(vtl[jj], Vsl + ad);
            }
            // pass 1: Ph*Vh
#pragma unroll
            for (int jj = 0; jj < 4; jj++) {
                unsigned bfr[2];
                bfr[0] = vth[jj][0]; bfr[1] = vth[jj][1];
                mma16816(o[2 * jj], ph, bfr);
                bfr[0] = vth[jj][2]; bfr[1] = vth[jj][3];
                mma16816(o[2 * jj + 1], ph, bfr);
            }
            // pass 2: Pl*Vh
#pragma unroll
            for (int jj = 0; jj < 4; jj++) {
                unsigned bfr[2];
                bfr[0] = vth[jj][0]; bfr[1] = vth[jj][1];
                mma16816(o[2 * jj], pl, bfr);
                bfr[0] = vth[jj][2]; bfr[1] = vth[jj][3];
                mma16816(o[2 * jj + 1], pl, bfr);
            }
            // pass 3: Ph*Vl
#pragma unroll
            for (int jj = 0; jj < 4; jj++) {
                unsigned bfr[2];
                bfr[0] = vtl[jj][0]; bfr[1] = vtl[jj][1];
                mma16816(o[2 * jj], ph, bfr);
                bfr[0] = vtl[jj][2]; bfr[1] = vtl[jj][3];
                mma16816(o[2 * jj + 1], ph, bfr);
            }
        }
    }

    const float inv0 = 1.0f / l0, inv1 = 1.0f / l1;
#pragma unroll
    for (int j = 0; j < 8; j++) {
        const size_t p0 = (size_t)(b * SEQ + qrow0) * 2048 + h * 64 + j * 8 + t2;
        unsigned hh, ll;
        f2bf_split(o[j][0] * inv0, o[j][1] * inv0, hh, ll);
        *(unsigned*)(Oh + p0) = hh;
        *(unsigned*)(Ol + p0) = ll;
        f2bf_split(o[j][2] * inv1, o[j][3] * inv1, hh, ll);
        *(unsigned*)(Oh + p0 + 8 * 2048) = hh;
        *(unsigned*)(Ol + p0 + 8 * 2048) = ll;
    }
}

// ---------------- host launcher -------------------------------------------
extern "C" void kernel_launch(void* const* d_in, const int* in_sizes, int n_in,
                              void* d_out, int out_size)
{
    const float* x    = (const float*)d_in[0];
    const int*   mask = (const int*)  d_in[1];
    const float* Wq   = (const float*)d_in[2];
    const float* Wk   = (const float*)d_in[3];
    const float* Wv   = (const float*)d_in[4];
    const float* Wo   = (const float*)d_in[5];
    float* out = (float*)d_out;

    void *pQ, *pK, *pV;
    void *pxh, *pxl, *pWqh, *pWql, *pWkh, *pWkl, *pWvh, *pWvl, *pWoh, *pWol;
    void *pQh, *pQl, *pKh, *pKl, *pVh, *pVl, *pOh, *pOl;
    cudaGetSymbolAddress(&pQ, g_Q);  cudaGetSymbolAddress(&pK, g_K);
    cudaGetSymbolAddress(&pV, g_V);
    cudaGetSymbolAddress(&pxh, g_xh);  cudaGetSymbolAddress(&pxl, g_xl);
    cudaGetSymbolAddress(&pWqh, g_Wqh); cudaGetSymbolAddress(&pWql, g_Wql);
    cudaGetSymbolAddress(&pWkh, g_Wkh); cudaGetSymbolAddress(&pWkl, g_Wkl);
    cudaGetSymbolAddress(&pWvh, g_Wvh); cudaGetSymbolAddress(&pWvl, g_Wvl);
    cudaGetSymbolAddress(&pWoh, g_Woh); cudaGetSymbolAddress(&pWol, g_Wol);
    cudaGetSymbolAddress(&pQh, g_Qh);   cudaGetSymbolAddress(&pQl, g_Ql);
    cudaGetSymbolAddress(&pKh, g_Kh);   cudaGetSymbolAddress(&pKl, g_Kl);
    cudaGetSymbolAddress(&pVh, g_Vh);   cudaGetSymbolAddress(&pVl, g_Vl);
    cudaGetSymbolAddress(&pOh, g_Oh);   cudaGetSymbolAddress(&pOl, g_Ol);

    init_freqs_kernel<<<1, 32>>>();

    // split fp32 operands into (hi, lo) bf16 planes
    split_kernel<<<(MROWS * DMODEL / 4) / 256, 256>>>(x,  (__nv_bfloat16*)pxh, (__nv_bfloat16*)pxl, MROWS * DMODEL / 4);
    split_kernel<<<(DMODEL * 2048 / 4) / 256, 256>>>(Wq, (__nv_bfloat16*)pWqh, (__nv_bfloat16*)pWql, DMODEL * 2048 / 4);
    split_kernel<<<(DMODEL * 512  / 4) / 256, 256>>>(Wk, (__nv_bfloat16*)pWkh, (__nv_bfloat16*)pWkl, DMODEL * 512 / 4);
    split_kernel<<<(DMODEL * 512  / 4) / 256, 256>>>(Wv, (__nv_bfloat16*)pWvh, (__nv_bfloat16*)pWvl, DMODEL * 512 / 4);
    split_kernel<<<(2048 * DMODEL / 4) / 256, 256>>>(Wo, (__nv_bfloat16*)pWoh, (__nv_bfloat16*)pWol, 2048 * DMODEL / 4);

    cudaFuncSetAttribute(gemm_bf16x3, cudaFuncAttributeMaxDynamicSharedMemorySize, GEMM_SMEM);

    // QKV projections (tensor cores)
    gemm_bf16x3<<<dim3(2048 / 128, MROWS / 128), 256, GEMM_SMEM>>>(
        (const __nv_bfloat16*)pxh, (const __nv_bfloat16*)pxl,
        (const __nv_bfloat16*)pWqh, (const __nv_bfloat16*)pWql,
        (float*)pQ, MROWS, 2048, DMODEL);
    gemm_bf16x3<<<dim3(512 / 128, MROWS / 128), 256, GEMM_SMEM>>>(
        (const __nv_bfloat16*)pxh, (const __nv_bfloat16*)pxl,
        (const __nv_bfloat16*)pWkh, (const __nv_bfloat16*)pWkl,
        (float*)pK, MROWS, 512, DMODEL);
    gemm_bf16x3<<<dim3(512 / 128, MROWS / 128), 256, GEMM_SMEM>>>(
        (const __nv_bfloat16*)pxh, (const __nv_bfloat16*)pxl,
        (const __nv_bfloat16*)pWvh, (const __nv_bfloat16*)pWvl,
        (float*)pV, MROWS, 512, DMODEL);

    // fused RoPE + split for Q and K; plain split for V
    rope_split_kernel<<<(MROWS * NHEADS  * 32) / 256, 256>>>(
        (const float*)pQ, (__nv_bfloat16*)pQh, (__nv_bfloat16*)pQl, NHEADS * HDIM, NHEADS);
    rope_split_kernel<<<(MROWS * KVHEADS * 32) / 256, 256>>>(
        (const float*)pK, (__nv_bfloat16*)pKh, (__nv_bfloat16*)pKl, KVHEADS * HDIM, KVHEADS);
    split_kernel<<<(MROWS * 512 / 4) / 256, 256>>>(
        (const float*)pV, (__nv_bfloat16*)pVh, (__nv_bfloat16*)pVl, MROWS * 512 / 4);

    // Flash attention (tensor cores, split-bf16)
    cudaFuncSetAttribute(flash_mma_kernel, cudaFuncAttributeMaxDynamicSharedMemorySize, FL_SMEM);
    flash_mma_kernel<<<dim3(SEQ / 64, NHEADS, BATCH), 128, FL_SMEM>>>(
        (const __nv_bfloat16*)pQh, (const __nv_bfloat16*)pQl,
        (const __nv_bfloat16*)pKh, (const __nv_bfloat16*)pKl,
        (const __nv_bfloat16*)pVh, (const __nv_bfloat16*)pVl,
        mask, (__nv_bfloat16*)pOh, (__nv_bfloat16*)pOl);

    // Output projection (tensor cores)
    gemm_bf16x3<<<dim3(2048 / 128, MROWS / 128), 256, GEMM_SMEM>>>(
        (const __nv_bfloat16*)pOh, (const __nv_bfloat16*)pOl,
        (const __nv_bfloat16*)pWoh, (const __nv_bfloat16*)pWol,
        out, MROWS, 2048, DMODEL);
}